// round 10
// baseline (speedup 1.0000x reference)
#include <cuda_runtime.h>
#include <cuda_bf16.h>
#include <math.h>

// ---------------- problem constants ----------------
#define BB    8
#define SS    2048
#define DD    512
#define MM    (BB*SS)          // 16384 rows
#define DM    (DD*4)           // 2048
#define KCONV 9
#define SPAD  (SS+8)           // 2056 padded rows per batch
#define NC    32               // scan chunks
#define LCH   (SS/NC)          // 64 steps per chunk

typedef __nv_bfloat16 bf16;
typedef __nv_bfloat162 bf162;

// ---------------- scratch (device globals; no allocs allowed) ----------------
__device__ bf16  g_xn  [MM*DD];
__device__ float g_l2  [MM*DD];
__device__ bf16  g_pad [BB*SPAD*DD];
__device__ bf16  g_conv[MM*DD];
__device__ bf16  g_xL  [MM*DD];
__device__ float g_R   [MM*DD];
__device__ float g_I   [MM*DD];
__device__ float g_x1  [MM*DD];
__device__ bf16  g_xn2 [MM*DD];
__device__ bf16  g_act [MM*DM];
__device__ bf16  g_Wc  [KCONV*DD*DD];
__device__ bf16  g_pwT [DD*DD];
__device__ float g_cA  [BB*NC*DD];
__device__ float g_cB  [BB*NC*DD];
__device__ float g_pref[BB*NC*DD];
__device__ float g_lamc[DD];
__device__ bf16  g_W12t[DD*2*DD];   // [K=512][1024]: cols 0..511 = W1, 512..1023 = W2
__device__ float g_b12 [2*DD];
__device__ bf16  g_Writ[DD*2*DD];   // interleaved [K=512][2*512]: 2d=Wr, 2d+1=Wi
__device__ float g_bri [2*DD];
__device__ bf16  g_Wm1t[DD*DM];
__device__ bf16  g_Wm2t[DD*DM];

// ---------------- helpers ----------------
__device__ __forceinline__ float gelu_exact(float v) {
    return 0.5f * v * (1.0f + erff(v * 0.70710678118654752f));
}

__device__ __forceinline__ void mma16(float* c, const unsigned* a, const unsigned* b) {
    asm volatile(
        "mma.sync.aligned.m16n8k16.row.col.f32.bf16.bf16.f32 "
        "{%0,%1,%2,%3}, {%4,%5,%6,%7}, {%8,%9}, {%0,%1,%2,%3};"
        : "+f"(c[0]), "+f"(c[1]), "+f"(c[2]), "+f"(c[3])
        : "r"(a[0]), "r"(a[1]), "r"(a[2]), "r"(a[3]), "r"(b[0]), "r"(b[1]));
}

__device__ __forceinline__ void ldsm4(unsigned* r, unsigned addr) {
    asm volatile("ldmatrix.sync.aligned.m8n8.x4.shared.b16 {%0,%1,%2,%3}, [%4];"
                 : "=r"(r[0]), "=r"(r[1]), "=r"(r[2]), "=r"(r[3]) : "r"(addr));
}
__device__ __forceinline__ void ldsm2t(unsigned* r, unsigned addr) {
    asm volatile("ldmatrix.sync.aligned.m8n8.x2.trans.shared.b16 {%0,%1}, [%2];"
                 : "=r"(r[0]), "=r"(r[1]) : "r"(addr));
}

__device__ __forceinline__ void cpacg(unsigned s, const void* g) {
    asm volatile("cp.async.cg.shared.global [%0], [%1], 16;" :: "r"(s), "l"(g));
}
__device__ __forceinline__ void cpa_commit() {
    asm volatile("cp.async.commit_group;");
}

// ---------------- RMS norm (f32 in -> bf16 out) ----------------
__global__ void rms_k(const float* __restrict__ x, const float* __restrict__ g,
                      bf16* __restrict__ o) {
    int row = blockIdx.x;
    int t = threadIdx.x;
    const float4* xr = (const float4*)(x + (size_t)row * DD);
    float4 v = xr[t];
    float s = v.x*v.x + v.y*v.y + v.z*v.z + v.w*v.w;
    #pragma unroll
    for (int off = 16; off; off >>= 1) s += __shfl_xor_sync(0xffffffffu, s, off);
    __shared__ float ws[4];
    if ((t & 31) == 0) ws[t >> 5] = s;
    __syncthreads();
    float tot = ws[0] + ws[1] + ws[2] + ws[3];
    float sc = 22.627416997969522f / (sqrtf(tot) + 1e-6f);
    float4 gv = ((const float4*)g)[t];
    bf162* ob = (bf162*)(o + (size_t)row * DD);
    ob[2*t]   = __floats2bfloat162_rn(v.x * sc * gv.x, v.y * sc * gv.y);
    ob[2*t+1] = __floats2bfloat162_rn(v.z * sc * gv.z, v.w * sc * gv.w);
}

// ---------------- bf16 tensor-core GEMM, 128x128 tile, BK=64, 2-stage ----------------
// EPI: 0 = bias, 2 = gelu(v)*v, 3 = +res, 4 = fused RG-LRU gates,
//      5 = dual W1/W2 (cols<512 -> bf16 pad w/ remap, cols>=512 -> f32 l2)
// CONV: A read from padded activations with tap offsets (K'=9*512)
// OUTBF: output bf16, else f32. PADOUT: padded-row output remap.
#define BM 128
#define BN 128
#define BK 64
#define APITCH 72      // 144B rows; ldsm phases conflict-free (16B*k mod 128 distinct)
#define BPITCH 136     // 272B rows
#define NSTG 2
#define SMEMSZ (NSTG*(BM*APITCH + BK*BPITCH)*2)

template <int EPI, bool CONV, bool OUTBF, bool PADOUT>
__global__ void __launch_bounds__(256, 2)
tgemm(const bf16* __restrict__ A, const bf16* __restrict__ Bw,
      const float* __restrict__ bias, float* __restrict__ res,
      const float* __restrict__ lamc, void* __restrict__ Cv,
      int M_, int N_, int K_) {
    extern __shared__ bf16 smb[];
    bf16 (*As)[BM][APITCH] = (bf16(*)[BM][APITCH])smb;
    bf16 (*Bs)[BK][BPITCH] = (bf16(*)[BK][BPITCH])(smb + NSTG * BM * APITCH);

    const int tid = threadIdx.x;
    const int m0 = blockIdx.y * BM;
    const int n0 = blockIdx.x * BN;
    const int warp = tid >> 5, lane = tid & 31;
    const int wm = (warp >> 2) * 64;
    const int wn = (warp & 3) * 32;
    const int padbase = CONV ? (m0 + 8 * (m0 / SS)) : 0;

    // cp.async staging maps (conflict-free per 8-lane phase)
    const int arow  = tid & 127;        // A row
    const int ahalf = tid >> 7;         // 0/1: which 64B half of the 128B row
    const int brow  = tid & 63;         // B (k) row
    const int bq    = tid >> 6;         // 0..3: which 64B quarter of the 256B row

    // ldmatrix lane offsets
    const int a_rowoff = (lane & 7) + ((lane >> 3) & 1) * 8;
    const int a_coloff = (lane >> 4) * 8;
    const int b_rowoff = lane & 15;

    const unsigned sA = (unsigned)__cvta_generic_to_shared(smb);
    const unsigned sB = (unsigned)__cvta_generic_to_shared(smb + NSTG * BM * APITCH);
    const unsigned aBase = sA + (unsigned)(((wm + a_rowoff) * APITCH + a_coloff) * 2);
    const unsigned bBase = sB + (unsigned)((b_rowoff * BPITCH + wn) * 2);

    const int nit = K_ / BK;

    auto prefetch = [&](int it, int buf) {
        int k0 = it * BK;
        const bf16* ga;
        if (CONV) {
            int tap = k0 >> 9;
            int kin = k0 & 511;
            ga = A + (size_t)(padbase + arow + tap) * DD + kin + ahalf * 32;
        } else {
            ga = A + (size_t)(m0 + arow) * K_ + k0 + ahalf * 32;
        }
        unsigned da = (unsigned)__cvta_generic_to_shared(&As[buf][arow][ahalf * 32]);
        #pragma unroll
        for (int u = 0; u < 4; u++) cpacg(da + u * 16, ga + u * 8);
        const bf16* gb = Bw + (size_t)(k0 + brow) * N_ + n0 + bq * 32;
        unsigned db = (unsigned)__cvta_generic_to_shared(&Bs[buf][brow][bq * 32]);
        #pragma unroll
        for (int u = 0; u < 4; u++) cpacg(db + u * 16, gb + u * 8);
        cpa_commit();
    };

    float acc[4][4][4] = {};

    prefetch(0, 0);

    for (int it = 0; it < nit; it++) {
        asm volatile("cp.async.wait_group 0;");
        __syncthreads();
        if (it + 1 < nit) prefetch(it + 1, (it + 1) & 1);

        const int buf = it & 1;
        const unsigned ab = aBase + (unsigned)(buf * BM * APITCH * 2);
        const unsigned bb = bBase + (unsigned)(buf * BK * BPITCH * 2);
        #pragma unroll
        for (int t = 0; t < 4; t++) {
            unsigned af[4][4], bfr[4][2];
            #pragma unroll
            for (int mi = 0; mi < 4; mi++)
                ldsm4(af[mi], ab + (unsigned)((mi * 16 * APITCH + 16 * t) * 2));
            #pragma unroll
            for (int ni = 0; ni < 4; ni++)
                ldsm2t(bfr[ni], bb + (unsigned)((16 * t * BPITCH + 8 * ni) * 2));
            #pragma unroll
            for (int mi = 0; mi < 4; mi++)
                #pragma unroll
                for (int ni = 0; ni < 4; ni++)
                    mma16(acc[mi][ni], af[mi], bfr[ni]);
        }
        // next iteration's top-of-loop barrier protects buffer reuse
    }

    // epilogue
    const int r = lane >> 2, cg = lane & 3;
    const int opitch = PADOUT ? DD : N_;
    #pragma unroll
    for (int mi = 0; mi < 4; mi++) {
        int mlo = m0 + wm + mi * 16 + r;
        int mhi = mlo + 8;
        int olo = PADOUT ? (mlo + 4 + 8 * (mlo >> 11)) : mlo;
        int ohi = PADOUT ? (mhi + 4 + 8 * (mhi >> 11)) : mhi;
        #pragma unroll
        for (int ni = 0; ni < 4; ni++) {
            int n = n0 + wn + ni * 8 + 2 * cg;
            float b0 = bias[n], b1 = bias[n + 1];
            float v0 = acc[mi][ni][0] + b0;
            float v1 = acc[mi][ni][1] + b1;
            float v2 = acc[mi][ni][2] + b0;
            float v3 = acc[mi][ni][3] + b1;
            if (EPI == 4) {
                int d = n >> 1;
                float lc = lamc[d];
                float r0 = 1.f / (1.f + __expf(-v0));
                float i0 = 1.f / (1.f + __expf(-v1));
                float r1 = 1.f / (1.f + __expf(-v2));
                float i1 = 1.f / (1.f + __expf(-v3));
                float a0 = __expf(lc * r0), a1 = __expf(lc * r1);
                float xl0 = __bfloat162float(A[(size_t)mlo * DD + d]);
                float xl1 = __bfloat162float(A[(size_t)mhi * DD + d]);
                float bb0 = sqrtf(fmaxf(0.f, 1.f - a0 * a0)) * i0 * xl0;
                float bb1 = sqrtf(fmaxf(0.f, 1.f - a1 * a1)) * i1 * xl1;
                float* Rp = (float*)Cv;
                Rp[(size_t)mlo * DD + d] = a0;
                Rp[(size_t)mhi * DD + d] = a1;
                res[(size_t)mlo * DD + d] = bb0;
                res[(size_t)mhi * DD + d] = bb1;
                continue;
            }
            if (EPI == 5) {
                if (n0 < DD) {
                    bf16* C = (bf16*)Cv;
                    int plo = mlo + 4 + 8 * (mlo >> 11);
                    int phi = mhi + 4 + 8 * (mhi >> 11);
                    *(bf162*)(C + (size_t)plo * DD + n) = __floats2bfloat162_rn(v0, v1);
                    *(bf162*)(C + (size_t)phi * DD + n) = __floats2bfloat162_rn(v2, v3);
                } else {
                    int c = n - DD;
                    *(float2*)(res + (size_t)mlo * DD + c) = make_float2(v0, v1);
                    *(float2*)(res + (size_t)mhi * DD + c) = make_float2(v2, v3);
                }
                continue;
            }
            if (EPI == 2) {
                v0 *= gelu_exact(v0); v1 *= gelu_exact(v1);
                v2 *= gelu_exact(v2); v3 *= gelu_exact(v3);
            } else if (EPI == 3) {
                float2 r0 = *(const float2*)(res + (size_t)mlo * N_ + n);
                float2 r1 = *(const float2*)(res + (size_t)mhi * N_ + n);
                v0 += r0.x; v1 += r0.y; v2 += r1.x; v3 += r1.y;
            }
            if (OUTBF) {
                bf16* C = (bf16*)Cv;
                *(bf162*)(C + (size_t)olo * opitch + n) = __floats2bfloat162_rn(v0, v1);
                *(bf162*)(C + (size_t)ohi * opitch + n) = __floats2bfloat162_rn(v2, v3);
            } else {
                float* C = (float*)Cv;
                *(float2*)(C + (size_t)olo * opitch + n) = make_float2(v0, v1);
                *(float2*)(C + (size_t)ohi * opitch + n) = make_float2(v2, v3);
            }
        }
    }
}

// ---------------- weight prep (merged, ranged dispatch) ----------------
// blocks [0,256)    : W1 -> W12t cols 0..511
// blocks [256,512)  : W2 -> W12t cols 512..1023
// blocks [512,1536) : Wm1 flat bf16
// blocks [1536,2560): Wm2 flat bf16
// blocks [2560,3584): pwT[i*512+o] = pw_w[o*512+i]
// blocks [3584,4608): Writ[k][2d]=Wr, [k][2d+1]=Wi
__global__ void prep_weights_k(const float* __restrict__ W1, const float* __restrict__ W2,
                               const float* __restrict__ Wm1, const float* __restrict__ Wm2,
                               const float* __restrict__ pw_w,
                               const float* __restrict__ Wr, const float* __restrict__ Wi,
                               bf16* __restrict__ W12t, bf16* __restrict__ Wm1t,
                               bf16* __restrict__ Wm2t, bf16* __restrict__ pwT,
                               bf16* __restrict__ Writ) {
    int b = blockIdx.x, tid = threadIdx.x;
    if (b < 512) {
        // W1/W2 -> W12t
        const float* s = (b < 256) ? W1 : W2;
        int coff = (b < 256) ? 0 : DD;
        int i = ((b & 255) * 256 + tid);            // float4 index, 65536 total
        float4 v = ((const float4*)s)[i];
        int k = i >> 7;
        int c = (i & 127) * 4 + coff;
        bf162* d = (bf162*)(W12t + (size_t)k * (2 * DD) + c);
        d[0] = __floats2bfloat162_rn(v.x, v.y);
        d[1] = __floats2bfloat162_rn(v.z, v.w);
        return;
    }
    if (b < 2560) {
        const float* s = (b < 1536) ? Wm1 : Wm2;
        bf16* d = (b < 1536) ? Wm1t : Wm2t;
        int j = ((b < 1536) ? (b - 512) : (b - 1536)) * 256 + tid;  // float4 idx, 262144
        float4 v = ((const float4*)s)[j];
        ((bf162*)d)[2*j]   = __floats2bfloat162_rn(v.x, v.y);
        ((bf162*)d)[2*j+1] = __floats2bfloat162_rn(v.z, v.w);
        return;
    }
    if (b < 3584) {
        int idx = (b - 2560) * 256 + tid;           // 262144 elements
        int o = idx % DD;
        int i = idx / DD;
        pwT[idx] = __float2bfloat16(pw_w[(size_t)o * DD + i]);
        return;
    }
    {
        int idx = (b - 3584) * 256 + tid;           // 262144 elements
        int k = idx / DD, d = idx % DD;
        Writ[(size_t)k * (2 * DD) + 2 * d]     = __float2bfloat16(Wr[idx]);
        Writ[(size_t)k * (2 * DD) + 2 * d + 1] = __float2bfloat16(Wi[idx]);
    }
}

// small vectors: bri (interleaved br,bi), b12 (concat b1,b2), lamc
__global__ void prep_small_k(const float* __restrict__ br, const float* __restrict__ bi,
                             const float* __restrict__ b1, const float* __restrict__ b2,
                             const float* __restrict__ lam,
                             float* __restrict__ bri, float* __restrict__ b12,
                             float* __restrict__ lamc) {
    int d = blockIdx.x * blockDim.x + threadIdx.x;
    if (d >= DD) return;
    bri[2 * d]     = br[d];
    bri[2 * d + 1] = bi[d];
    b12[d]        = b1[d];
    b12[DD + d]   = b2[d];
    float l = lam[d];
    float sp = (l > 15.f) ? l : log1pf(expf(l));
    lamc[d] = -8.0f * sp;
}

// transpose dw_w (o,i,k) -> Wc[k][i][o] via smem tiles
__global__ void prep_wc_k(const float* __restrict__ dw_w, bf16* __restrict__ Wc) {
    __shared__ bf16 s[1024][10];   // [o_local*32 + i_local][k]
    int o0 = (blockIdx.x & 15) * 32;
    int i0 = (blockIdx.x >> 4) * 32;
    int t = threadIdx.x;           // 256 threads
    for (int p = t; p < 1024; p += 256) {
        int ol = p >> 5, il = p & 31;
        const float* src = dw_w + ((size_t)(o0 + ol) * DD + (i0 + il)) * KCONV;
        #pragma unroll
        for (int k = 0; k < KCONV; k++) s[p][k] = __float2bfloat16(src[k]);
    }
    __syncthreads();
    #pragma unroll
    for (int k = 0; k < KCONV; k++) {
        for (int e = t; e < 1024; e += 256) {
            int il = e >> 5, ol = e & 31;
            Wc[(size_t)k * DD * DD + (size_t)(i0 + il) * DD + (o0 + ol)] = s[ol * 32 + il][k];
        }
    }
}

__global__ void zero_edges_k(bf16* __restrict__ pad) {
    int idx = blockIdx.x * blockDim.x + threadIdx.x;
    if (idx >= BB * 8 * (DD / 8)) return;
    int c = idx & 63;
    int rr = idx >> 6;
    int b = rr >> 3, j = rr & 7;
    int p = (j < 4) ? j : (2048 + j);
    uint4 z = make_uint4(0, 0, 0, 0);
    *(uint4*)(pad + ((size_t)b * SPAD + p) * DD + c * 8) = z;
}

// ---------------- chunked linear scan ----------------
__global__ void scanA_k(const float* __restrict__ a, const float* __restrict__ b,
                        float* __restrict__ cA, float* __restrict__ cB) {
    int t = blockIdx.x * blockDim.x + threadIdx.x;
    if (t >= BB * NC * DD) return;
    int d = t & (DD - 1);
    int chunk = (t >> 9) & (NC - 1);
    int batch = t >> 14;
    size_t base = ((size_t)batch * SS + (size_t)chunk * LCH) * DD + d;
    float A = 1.f, Bv = 0.f;
    for (int s = 0; s < LCH; s++) {
        float av = a[base + (size_t)s * DD];
        float bv = b[base + (size_t)s * DD];
        Bv = av * Bv + bv;
        A *= av;
    }
    cA[t] = A; cB[t] = Bv;
}

__global__ void scanB_k(const float* __restrict__ cA, const float* __restrict__ cB,
                        float* __restrict__ pref) {
    int t = blockIdx.x * blockDim.x + threadIdx.x;
    if (t >= BB * DD) return;
    int d = t & (DD - 1);
    int batch = t >> 9;
    float h = 0.f;
    for (int c = 0; c < NC; c++) {
        size_t idx = ((size_t)batch * NC + c) * DD + d;
        pref[idx] = h;
        h = cA[idx] * h + cB[idx];
    }
}

__global__ void scanC_k(const float* __restrict__ a, const float* __restrict__ b,
                        const float* __restrict__ pref, const float* __restrict__ l2,
                        const float* __restrict__ skip, float* __restrict__ x1) {
    int t = blockIdx.x * blockDim.x + threadIdx.x;
    if (t >= BB * NC * DD) return;
    int d = t & (DD - 1);
    int chunk = (t >> 9) & (NC - 1);
    int batch = t >> 14;
    size_t base = ((size_t)batch * SS + (size_t)chunk * LCH) * DD + d;
    float h = pref[t];
    for (int s = 0; s < LCH; s++) {
        size_t idx = base + (size_t)s * DD;
        h = a[idx] * h + b[idx];
        x1[idx] = h * gelu_exact(l2[idx]) + skip[idx];
    }
}

// ---------------- launch ----------------
extern "C" void kernel_launch(void* const* d_in, const int* in_sizes, int n_in,
                              void* d_out, int out_size) {
    const float* x    = (const float*)d_in[0];
    const float* g    = (const float*)d_in[1];
    const float* W1   = (const float*)d_in[2];
    const float* b1   = (const float*)d_in[3];
    const float* W2   = (const float*)d_in[4];
    const float* b2   = (const float*)d_in[5];
    const float* dw_w = (const float*)d_in[6];
    const float* dw_b = (const float*)d_in[7];
    const float* pw_w = (const float*)d_in[8];
    const float* pw_b = (const float*)d_in[9];
    const float* Wi   = (const float*)d_in[10];
    const float* bi   = (const float*)d_in[11];
    const float* Wr   = (const float*)d_in[12];
    const float* br   = (const float*)d_in[13];
    const float* lam  = (const float*)d_in[14];
    const float* Wm1  = (const float*)d_in[15];
    const float* bm1  = (const float*)d_in[16];
    const float* Wm2  = (const float*)d_in[17];
    const float* bm2  = (const float*)d_in[18];
    float* out = (float*)d_out;

    bf16 *xn, *pad, *conv, *xL, *xn2, *act, *Wc, *pwT;
    bf16 *W12t, *Writ, *Wm1t, *Wm2t;
    float *l2, *R, *I, *x1, *cA, *cB, *pref, *lamc, *bri, *b12;
    cudaGetSymbolAddress((void**)&xn,   g_xn);
    cudaGetSymbolAddress((void**)&l2,   g_l2);
    cudaGetSymbolAddress((void**)&pad,  g_pad);
    cudaGetSymbolAddress((void**)&conv, g_conv);
    cudaGetSymbolAddress((void**)&xL,   g_xL);
    cudaGetSymbolAddress((void**)&R,    g_R);
    cudaGetSymbolAddress((void**)&I,    g_I);
    cudaGetSymbolAddress((void**)&x1,   g_x1);
    cudaGetSymbolAddress((void**)&xn2,  g_xn2);
    cudaGetSymbolAddress((void**)&act,  g_act);
    cudaGetSymbolAddress((void**)&Wc,   g_Wc);
    cudaGetSymbolAddress((void**)&pwT,  g_pwT);
    cudaGetSymbolAddress((void**)&cA,   g_cA);
    cudaGetSymbolAddress((void**)&cB,   g_cB);
    cudaGetSymbolAddress((void**)&pref, g_pref);
    cudaGetSymbolAddress((void**)&lamc, g_lamc);
    cudaGetSymbolAddress((void**)&W12t, g_W12t);
    cudaGetSymbolAddress((void**)&b12,  g_b12);
    cudaGetSymbolAddress((void**)&Writ, g_Writ);
    cudaGetSymbolAddress((void**)&bri,  g_bri);
    cudaGetSymbolAddress((void**)&Wm1t, g_Wm1t);
    cudaGetSymbolAddress((void**)&Wm2t, g_Wm2t);

    cudaFuncSetAttribute(tgemm<5,false,false,false>, cudaFuncAttributeMaxDynamicSharedMemorySize, SMEMSZ);
    cudaFuncSetAttribute(tgemm<0,true ,true ,false>, cudaFuncAttributeMaxDynamicSharedMemorySize, SMEMSZ);
    cudaFuncSetAttribute(tgemm<0,false,true ,false>, cudaFuncAttributeMaxDynamicSharedMemorySize, SMEMSZ);
    cudaFuncSetAttribute(tgemm<4,false,false,false>, cudaFuncAttributeMaxDynamicSharedMemorySize, SMEMSZ);
    cudaFuncSetAttribute(tgemm<2,false,true ,false>, cudaFuncAttributeMaxDynamicSharedMemorySize, SMEMSZ);
    cudaFuncSetAttribute(tgemm<3,false,false,false>, cudaFuncAttributeMaxDynamicSharedMemorySize, SMEMSZ);

    dim3 g512 (DD / BN, MM / BM);          // (4, 128)
    dim3 g1024(2 * DD / BN, MM / BM);      // (8, 128)
    dim3 g2048(DM / BN, MM / BM);          // (16, 128)

    // ---- weight prep ----
    prep_weights_k<<<4608, 256>>>(W1, W2, Wm1, Wm2, pw_w, Wr, Wi,
                                  W12t, Wm1t, Wm2t, pwT, Writ);
    prep_small_k<<<2, 256>>>(br, bi, b1, b2, lam, bri, b12, lamc);
    prep_wc_k<<<256, 256>>>(dw_w, Wc);
    zero_edges_k<<<(BB * 8 * (DD/8) + 255) / 256, 256>>>(pad);

    // ---- block 1 ----
    rms_k<<<MM, 128>>>(x, g, xn);
    tgemm<5,false,false,false><<<g1024, 256, SMEMSZ>>>(xn, W12t, b12, l2, nullptr, pad, MM, 2 * DD, DD);
    tgemm<0,true ,true ,false><<<g512, 256, SMEMSZ>>>(pad, Wc, dw_b, nullptr, nullptr, conv, MM, DD, KCONV * DD);
    tgemm<0,false,true ,false><<<g512, 256, SMEMSZ>>>(conv, pwT, pw_b, nullptr, nullptr, xL, MM, DD, DD);
    tgemm<4,false,false,false><<<g1024, 256, SMEMSZ>>>(xL, Writ, bri, I, lamc, R, MM, 2 * DD, DD);
    scanA_k<<<(BB * NC * DD + 255) / 256, 256>>>(R, I, cA, cB);
    scanB_k<<<(BB * DD + 255) / 256, 256>>>(cA, cB, pref);
    scanC_k<<<(BB * NC * DD + 255) / 256, 256>>>(R, I, pref, l2, x, x1);

    // ---- block 2 (MLP) ----
    rms_k<<<MM, 128>>>(x1, g, xn2);
    tgemm<2,false,true ,false><<<g2048, 256, SMEMSZ>>>(xn2, Wm1t, bm1, nullptr, nullptr, act, MM, DM, DD);
    tgemm<3,false,false,false><<<g512, 256, SMEMSZ>>>(act, Wm2t, bm2, x1, nullptr, out, MM, DD, DM);
}

// round 11
// speedup vs baseline: 1.3003x; 1.3003x over previous
#include <cuda_runtime.h>
#include <cuda_bf16.h>
#include <math.h>

// ---------------- problem constants ----------------
#define BB    8
#define SS    2048
#define DD    512
#define MM    (BB*SS)          // 16384 rows
#define DM    (DD*4)           // 2048
#define KCONV 9
#define SPAD  (SS+8)           // 2056 padded rows per batch
#define NC    32               // scan chunks
#define LCH   (SS/NC)          // 64 steps per chunk

typedef __nv_bfloat16 bf16;
typedef __nv_bfloat162 bf162;

// ---------------- scratch (device globals; no allocs allowed) ----------------
__device__ bf16  g_xn  [MM*DD];
__device__ float g_l2  [MM*DD];
__device__ bf16  g_pad [BB*SPAD*DD];
__device__ bf16  g_conv[MM*DD];
__device__ bf16  g_xL  [MM*DD];
__device__ float g_R   [MM*DD];
__device__ float g_I   [MM*DD];
__device__ float g_x1  [MM*DD];
__device__ bf16  g_xn2 [MM*DD];
__device__ bf16  g_act [MM*DM];
__device__ bf16  g_Wc  [KCONV*DD*DD];
__device__ bf16  g_pwT [DD*DD];
__device__ float g_cA  [BB*NC*DD];
__device__ float g_cB  [BB*NC*DD];
__device__ float g_pref[BB*NC*DD];
__device__ float g_lamc[DD];
__device__ bf16  g_W12t[DD*2*DD];   // [K=512][1024]: cols 0..511 = W1, 512..1023 = W2
__device__ float g_b12 [2*DD];
__device__ bf16  g_Writ[DD*2*DD];   // interleaved [K=512][2*512]: 2d=Wr, 2d+1=Wi
__device__ float g_bri [2*DD];
__device__ bf16  g_Wm1t[DD*DM];
__device__ bf16  g_Wm2t[DD*DM];

// ---------------- helpers ----------------
__device__ __forceinline__ float gelu_exact(float v) {
    return 0.5f * v * (1.0f + erff(v * 0.70710678118654752f));
}

__device__ __forceinline__ void mma16(float* c, const unsigned* a, const unsigned* b) {
    asm volatile(
        "mma.sync.aligned.m16n8k16.row.col.f32.bf16.bf16.f32 "
        "{%0,%1,%2,%3}, {%4,%5,%6,%7}, {%8,%9}, {%0,%1,%2,%3};"
        : "+f"(c[0]), "+f"(c[1]), "+f"(c[2]), "+f"(c[3])
        : "r"(a[0]), "r"(a[1]), "r"(a[2]), "r"(a[3]), "r"(b[0]), "r"(b[1]));
}

__device__ __forceinline__ void ldsm4(unsigned* r, unsigned addr) {
    asm volatile("ldmatrix.sync.aligned.m8n8.x4.shared.b16 {%0,%1,%2,%3}, [%4];"
                 : "=r"(r[0]), "=r"(r[1]), "=r"(r[2]), "=r"(r[3]) : "r"(addr));
}
__device__ __forceinline__ void ldsm2t(unsigned* r, unsigned addr) {
    asm volatile("ldmatrix.sync.aligned.m8n8.x2.trans.shared.b16 {%0,%1}, [%2];"
                 : "=r"(r[0]), "=r"(r[1]) : "r"(addr));
}

__device__ __forceinline__ void cpa16(unsigned s, const void* g) {
    asm volatile("cp.async.ca.shared.global [%0], [%1], 16;" :: "r"(s), "l"(g));
}
__device__ __forceinline__ void cpa_commit() {
    asm volatile("cp.async.commit_group;");
}

// ---------------- RMS norm (f32 in -> bf16 out) ----------------
__global__ void rms_k(const float* __restrict__ x, const float* __restrict__ g,
                      bf16* __restrict__ o) {
    int row = blockIdx.x;
    int t = threadIdx.x;
    const float4* xr = (const float4*)(x + (size_t)row * DD);
    float4 v = xr[t];
    float s = v.x*v.x + v.y*v.y + v.z*v.z + v.w*v.w;
    #pragma unroll
    for (int off = 16; off; off >>= 1) s += __shfl_xor_sync(0xffffffffu, s, off);
    __shared__ float ws[4];
    if ((t & 31) == 0) ws[t >> 5] = s;
    __syncthreads();
    float tot = ws[0] + ws[1] + ws[2] + ws[3];
    float sc = 22.627416997969522f / (sqrtf(tot) + 1e-6f);
    float4 gv = ((const float4*)g)[t];
    bf162* ob = (bf162*)(o + (size_t)row * DD);
    ob[2*t]   = __floats2bfloat162_rn(v.x * sc * gv.x, v.y * sc * gv.y);
    ob[2*t+1] = __floats2bfloat162_rn(v.z * sc * gv.z, v.w * sc * gv.w);
}

// ---------------- bf16 tensor-core GEMM, 128x128 tile (round-8 proven config) ----------------
// EPI: 0 = bias, 2 = gelu(v)*v, 3 = +res, 4 = fused RG-LRU gates,
//      5 = dual W1/W2 (cols<512 -> bf16 pad w/ remap, cols>=512 -> f32 l2)
// CONV: A read from padded activations with tap offsets (K'=9*512)
// OUTBF: output bf16, else f32. PADOUT: padded-row output remap.
#define BM 128
#define BN 128
#define BK 32
#define APITCH 40      // 80B rows, conflict-free ldsm
#define BPITCH 136     // 272B rows
#define NSTG 3
#define SMEMSZ (NSTG*(BM*APITCH + BK*BPITCH)*2)

template <int EPI, bool CONV, bool OUTBF, bool PADOUT>
__global__ void __launch_bounds__(256, 2)
tgemm(const bf16* __restrict__ A, const bf16* __restrict__ Bw,
      const float* __restrict__ bias, float* __restrict__ res,
      const float* __restrict__ lamc, void* __restrict__ Cv,
      int M_, int N_, int K_) {
    extern __shared__ bf16 smb[];
    bf16 (*As)[BM][APITCH] = (bf16(*)[BM][APITCH])smb;
    bf16 (*Bs)[BK][BPITCH] = (bf16(*)[BK][BPITCH])(smb + NSTG * BM * APITCH);

    const int tid = threadIdx.x;
    const int m0 = blockIdx.y * BM;
    const int n0 = blockIdx.x * BN;
    const int warp = tid >> 5, lane = tid & 31;
    const int wm = (warp >> 2) * 64;
    const int wn = (warp & 3) * 32;
    const int padbase = CONV ? (m0 + 8 * (m0 / SS)) : 0;

    // cp.async staging
    const int arow = tid >> 1;          // 0..127
    const int acol = (tid & 1) * 16;    // 0 or 16
    const int brow = tid >> 3;          // 0..31
    const int bcol = (tid & 7) * 16;    // 0..112

    // ldmatrix lane offsets
    const int a_rowoff = (lane & 7) + ((lane >> 3) & 1) * 8;
    const int a_coloff = (lane >> 4) * 8;
    const int b_rowoff = lane & 15;

    const unsigned sA = (unsigned)__cvta_generic_to_shared(smb);
    const unsigned sB = (unsigned)__cvta_generic_to_shared(smb + NSTG * BM * APITCH);
    const unsigned aBase = sA + (unsigned)(((wm + a_rowoff) * APITCH + a_coloff) * 2);
    const unsigned bBase = sB + (unsigned)((b_rowoff * BPITCH + wn) * 2);

    const int nit = K_ / BK;

    auto prefetch = [&](int it, int buf) {
        int k0 = it * BK;
        const bf16* ga;
        if (CONV) {
            int tap = k0 >> 9;
            int kin = k0 & 511;
            ga = A + (size_t)(padbase + arow + tap) * DD + kin + acol;
        } else {
            ga = A + (size_t)(m0 + arow) * K_ + k0 + acol;
        }
        unsigned da = (unsigned)__cvta_generic_to_shared(&As[buf][arow][acol]);
        cpa16(da, ga);
        cpa16(da + 16, ga + 8);
        const bf16* gb = Bw + (size_t)(k0 + brow) * N_ + n0 + bcol;
        unsigned db = (unsigned)__cvta_generic_to_shared(&Bs[buf][brow][bcol]);
        cpa16(db, gb);
        cpa16(db + 16, gb + 8);
    };

    float acc[4][4][4] = {};

    prefetch(0, 0); cpa_commit();
    if (nit > 1) { prefetch(1, 1); cpa_commit(); }

    for (int it = 0; it < nit; it++) {
        if (it + 1 < nit) asm volatile("cp.async.wait_group 1;");
        else              asm volatile("cp.async.wait_group 0;");
        __syncthreads();
        if (it + 2 < nit) { prefetch(it + 2, (it + 2) % NSTG); cpa_commit(); }

        const int buf = it % NSTG;
        const unsigned ab = aBase + (unsigned)(buf * BM * APITCH * 2);
        const unsigned bb = bBase + (unsigned)(buf * BK * BPITCH * 2);
        #pragma unroll
        for (int t = 0; t < 2; t++) {
            unsigned af[4][4], bfr[4][2];
            #pragma unroll
            for (int mi = 0; mi < 4; mi++)
                ldsm4(af[mi], ab + (unsigned)((mi * 16 * APITCH + 16 * t) * 2));
            #pragma unroll
            for (int ni = 0; ni < 4; ni++)
                ldsm2t(bfr[ni], bb + (unsigned)((16 * t * BPITCH + 8 * ni) * 2));
            #pragma unroll
            for (int mi = 0; mi < 4; mi++)
                #pragma unroll
                for (int ni = 0; ni < 4; ni++)
                    mma16(acc[mi][ni], af[mi], bfr[ni]);
        }
        // single barrier per iteration is sufficient with NSTG=3
    }

    // epilogue
    const int r = lane >> 2, cg = lane & 3;
    const int opitch = PADOUT ? DD : N_;
    #pragma unroll
    for (int mi = 0; mi < 4; mi++) {
        int mlo = m0 + wm + mi * 16 + r;
        int mhi = mlo + 8;
        int olo = PADOUT ? (mlo + 4 + 8 * (mlo >> 11)) : mlo;
        int ohi = PADOUT ? (mhi + 4 + 8 * (mhi >> 11)) : mhi;
        #pragma unroll
        for (int ni = 0; ni < 4; ni++) {
            int n = n0 + wn + ni * 8 + 2 * cg;
            float b0 = bias[n], b1 = bias[n + 1];
            float v0 = acc[mi][ni][0] + b0;
            float v1 = acc[mi][ni][1] + b1;
            float v2 = acc[mi][ni][2] + b0;
            float v3 = acc[mi][ni][3] + b1;
            if (EPI == 4) {
                int d = n >> 1;
                float lc = lamc[d];
                float r0 = 1.f / (1.f + __expf(-v0));
                float i0 = 1.f / (1.f + __expf(-v1));
                float r1 = 1.f / (1.f + __expf(-v2));
                float i1 = 1.f / (1.f + __expf(-v3));
                float a0 = __expf(lc * r0), a1 = __expf(lc * r1);
                float xl0 = __bfloat162float(A[(size_t)mlo * DD + d]);
                float xl1 = __bfloat162float(A[(size_t)mhi * DD + d]);
                float bb0 = sqrtf(fmaxf(0.f, 1.f - a0 * a0)) * i0 * xl0;
                float bb1 = sqrtf(fmaxf(0.f, 1.f - a1 * a1)) * i1 * xl1;
                float* Rp = (float*)Cv;
                Rp[(size_t)mlo * DD + d] = a0;
                Rp[(size_t)mhi * DD + d] = a1;
                res[(size_t)mlo * DD + d] = bb0;
                res[(size_t)mhi * DD + d] = bb1;
                continue;
            }
            if (EPI == 5) {
                if (n0 < DD) {
                    bf16* C = (bf16*)Cv;
                    int plo = mlo + 4 + 8 * (mlo >> 11);
                    int phi = mhi + 4 + 8 * (mhi >> 11);
                    *(bf162*)(C + (size_t)plo * DD + n) = __floats2bfloat162_rn(v0, v1);
                    *(bf162*)(C + (size_t)phi * DD + n) = __floats2bfloat162_rn(v2, v3);
                } else {
                    int c = n - DD;
                    *(float2*)(res + (size_t)mlo * DD + c) = make_float2(v0, v1);
                    *(float2*)(res + (size_t)mhi * DD + c) = make_float2(v2, v3);
                }
                continue;
            }
            if (EPI == 2) {
                v0 *= gelu_exact(v0); v1 *= gelu_exact(v1);
                v2 *= gelu_exact(v2); v3 *= gelu_exact(v3);
            } else if (EPI == 3) {
                float2 r0 = *(const float2*)(res + (size_t)mlo * N_ + n);
                float2 r1 = *(const float2*)(res + (size_t)mhi * N_ + n);
                v0 += r0.x; v1 += r0.y; v2 += r1.x; v3 += r1.y;
            }
            if (OUTBF) {
                bf16* C = (bf16*)Cv;
                *(bf162*)(C + (size_t)olo * opitch + n) = __floats2bfloat162_rn(v0, v1);
                *(bf162*)(C + (size_t)ohi * opitch + n) = __floats2bfloat162_rn(v2, v3);
            } else {
                float* C = (float*)Cv;
                *(float2*)(C + (size_t)olo * opitch + n) = make_float2(v0, v1);
                *(float2*)(C + (size_t)ohi * opitch + n) = make_float2(v2, v3);
            }
        }
    }
}

// ---------------- weight prep (merged, ranged dispatch) ----------------
// blocks [0,256)    : W1 -> W12t cols 0..511
// blocks [256,512)  : W2 -> W12t cols 512..1023
// blocks [512,1536) : Wm1 flat bf16
// blocks [1536,2560): Wm2 flat bf16
// blocks [2560,3584): pwT[i*512+o] = pw_w[o*512+i]
// blocks [3584,4608): Writ[k][2d]=Wr, [k][2d+1]=Wi
__global__ void prep_weights_k(const float* __restrict__ W1, const float* __restrict__ W2,
                               const float* __restrict__ Wm1, const float* __restrict__ Wm2,
                               const float* __restrict__ pw_w,
                               const float* __restrict__ Wr, const float* __restrict__ Wi,
                               bf16* __restrict__ W12t, bf16* __restrict__ Wm1t,
                               bf16* __restrict__ Wm2t, bf16* __restrict__ pwT,
                               bf16* __restrict__ Writ) {
    int b = blockIdx.x, tid = threadIdx.x;
    if (b < 512) {
        const float* s = (b < 256) ? W1 : W2;
        int coff = (b < 256) ? 0 : DD;
        int i = ((b & 255) * 256 + tid);            // float4 index, 65536 total
        float4 v = ((const float4*)s)[i];
        int k = i >> 7;
        int c = (i & 127) * 4 + coff;
        bf162* d = (bf162*)(W12t + (size_t)k * (2 * DD) + c);
        d[0] = __floats2bfloat162_rn(v.x, v.y);
        d[1] = __floats2bfloat162_rn(v.z, v.w);
        return;
    }
    if (b < 2560) {
        const float* s = (b < 1536) ? Wm1 : Wm2;
        bf16* d = (b < 1536) ? Wm1t : Wm2t;
        int j = ((b < 1536) ? (b - 512) : (b - 1536)) * 256 + tid;  // float4 idx, 262144
        float4 v = ((const float4*)s)[j];
        ((bf162*)d)[2*j]   = __floats2bfloat162_rn(v.x, v.y);
        ((bf162*)d)[2*j+1] = __floats2bfloat162_rn(v.z, v.w);
        return;
    }
    if (b < 3584) {
        int idx = (b - 2560) * 256 + tid;           // 262144 elements
        int o = idx % DD;
        int i = idx / DD;
        pwT[idx] = __float2bfloat16(pw_w[(size_t)o * DD + i]);
        return;
    }
    {
        int idx = (b - 3584) * 256 + tid;           // 262144 elements
        int k = idx / DD, d = idx % DD;
        Writ[(size_t)k * (2 * DD) + 2 * d]     = __float2bfloat16(Wr[idx]);
        Writ[(size_t)k * (2 * DD) + 2 * d + 1] = __float2bfloat16(Wi[idx]);
    }
}

// small vectors: bri (interleaved br,bi), b12 (concat b1,b2), lamc
__global__ void prep_small_k(const float* __restrict__ br, const float* __restrict__ bi,
                             const float* __restrict__ b1, const float* __restrict__ b2,
                             const float* __restrict__ lam,
                             float* __restrict__ bri, float* __restrict__ b12,
                             float* __restrict__ lamc) {
    int d = blockIdx.x * blockDim.x + threadIdx.x;
    if (d >= DD) return;
    bri[2 * d]     = br[d];
    bri[2 * d + 1] = bi[d];
    b12[d]        = b1[d];
    b12[DD + d]   = b2[d];
    float l = lam[d];
    float sp = (l > 15.f) ? l : log1pf(expf(l));
    lamc[d] = -8.0f * sp;
}

// transpose dw_w (o,i,k) -> Wc[k][i][o] via smem tiles
__global__ void prep_wc_k(const float* __restrict__ dw_w, bf16* __restrict__ Wc) {
    __shared__ bf16 s[1024][10];   // [o_local*32 + i_local][k]
    int o0 = (blockIdx.x & 15) * 32;
    int i0 = (blockIdx.x >> 4) * 32;
    int t = threadIdx.x;           // 256 threads
    for (int p = t; p < 1024; p += 256) {
        int ol = p >> 5, il = p & 31;
        const float* src = dw_w + ((size_t)(o0 + ol) * DD + (i0 + il)) * KCONV;
        #pragma unroll
        for (int k = 0; k < KCONV; k++) s[p][k] = __float2bfloat16(src[k]);
    }
    __syncthreads();
    #pragma unroll
    for (int k = 0; k < KCONV; k++) {
        for (int e = t; e < 1024; e += 256) {
            int il = e >> 5, ol = e & 31;
            Wc[(size_t)k * DD * DD + (size_t)(i0 + il) * DD + (o0 + ol)] = s[ol * 32 + il][k];
        }
    }
}

__global__ void zero_edges_k(bf16* __restrict__ pad) {
    int idx = blockIdx.x * blockDim.x + threadIdx.x;
    if (idx >= BB * 8 * (DD / 8)) return;
    int c = idx & 63;
    int rr = idx >> 6;
    int b = rr >> 3, j = rr & 7;
    int p = (j < 4) ? j : (2048 + j);
    uint4 z = make_uint4(0, 0, 0, 0);
    *(uint4*)(pad + ((size_t)b * SPAD + p) * DD + c * 8) = z;
}

// ---------------- chunked linear scan ----------------
__global__ void scanA_k(const float* __restrict__ a, const float* __restrict__ b,
                        float* __restrict__ cA, float* __restrict__ cB) {
    int t = blockIdx.x * blockDim.x + threadIdx.x;
    if (t >= BB * NC * DD) return;
    int d = t & (DD - 1);
    int chunk = (t >> 9) & (NC - 1);
    int batch = t >> 14;
    size_t base = ((size_t)batch * SS + (size_t)chunk * LCH) * DD + d;
    float A = 1.f, Bv = 0.f;
    for (int s = 0; s < LCH; s++) {
        float av = a[base + (size_t)s * DD];
        float bv = b[base + (size_t)s * DD];
        Bv = av * Bv + bv;
        A *= av;
    }
    cA[t] = A; cB[t] = Bv;
}

__global__ void scanB_k(const float* __restrict__ cA, const float* __restrict__ cB,
                        float* __restrict__ pref) {
    int t = blockIdx.x * blockDim.x + threadIdx.x;
    if (t >= BB * DD) return;
    int d = t & (DD - 1);
    int batch = t >> 9;
    float h = 0.f;
    for (int c = 0; c < NC; c++) {
        size_t idx = ((size_t)batch * NC + c) * DD + d;
        pref[idx] = h;
        h = cA[idx] * h + cB[idx];
    }
}

__global__ void scanC_k(const float* __restrict__ a, const float* __restrict__ b,
                        const float* __restrict__ pref, const float* __restrict__ l2,
                        const float* __restrict__ skip, float* __restrict__ x1) {
    int t = blockIdx.x * blockDim.x + threadIdx.x;
    if (t >= BB * NC * DD) return;
    int d = t & (DD - 1);
    int chunk = (t >> 9) & (NC - 1);
    int batch = t >> 14;
    size_t base = ((size_t)batch * SS + (size_t)chunk * LCH) * DD + d;
    float h = pref[t];
    for (int s = 0; s < LCH; s++) {
        size_t idx = base + (size_t)s * DD;
        h = a[idx] * h + b[idx];
        x1[idx] = h * gelu_exact(l2[idx]) + skip[idx];
    }
}

// ---------------- launch ----------------
extern "C" void kernel_launch(void* const* d_in, const int* in_sizes, int n_in,
                              void* d_out, int out_size) {
    const float* x    = (const float*)d_in[0];
    const float* g    = (const float*)d_in[1];
    const float* W1   = (const float*)d_in[2];
    const float* b1   = (const float*)d_in[3];
    const float* W2   = (const float*)d_in[4];
    const float* b2   = (const float*)d_in[5];
    const float* dw_w = (const float*)d_in[6];
    const float* dw_b = (const float*)d_in[7];
    const float* pw_w = (const float*)d_in[8];
    const float* pw_b = (const float*)d_in[9];
    const float* Wi   = (const float*)d_in[10];
    const float* bi   = (const float*)d_in[11];
    const float* Wr   = (const float*)d_in[12];
    const float* br   = (const float*)d_in[13];
    const float* lam  = (const float*)d_in[14];
    const float* Wm1  = (const float*)d_in[15];
    const float* bm1  = (const float*)d_in[16];
    const float* Wm2  = (const float*)d_in[17];
    const float* bm2  = (const float*)d_in[18];
    float* out = (float*)d_out;

    bf16 *xn, *pad, *conv, *xL, *xn2, *act, *Wc, *pwT;
    bf16 *W12t, *Writ, *Wm1t, *Wm2t;
    float *l2, *R, *I, *x1, *cA, *cB, *pref, *lamc, *bri, *b12;
    cudaGetSymbolAddress((void**)&xn,   g_xn);
    cudaGetSymbolAddress((void**)&l2,   g_l2);
    cudaGetSymbolAddress((void**)&pad,  g_pad);
    cudaGetSymbolAddress((void**)&conv, g_conv);
    cudaGetSymbolAddress((void**)&xL,   g_xL);
    cudaGetSymbolAddress((void**)&R,    g_R);
    cudaGetSymbolAddress((void**)&I,    g_I);
    cudaGetSymbolAddress((void**)&x1,   g_x1);
    cudaGetSymbolAddress((void**)&xn2,  g_xn2);
    cudaGetSymbolAddress((void**)&act,  g_act);
    cudaGetSymbolAddress((void**)&Wc,   g_Wc);
    cudaGetSymbolAddress((void**)&pwT,  g_pwT);
    cudaGetSymbolAddress((void**)&cA,   g_cA);
    cudaGetSymbolAddress((void**)&cB,   g_cB);
    cudaGetSymbolAddress((void**)&pref, g_pref);
    cudaGetSymbolAddress((void**)&lamc, g_lamc);
    cudaGetSymbolAddress((void**)&W12t, g_W12t);
    cudaGetSymbolAddress((void**)&b12,  g_b12);
    cudaGetSymbolAddress((void**)&Writ, g_Writ);
    cudaGetSymbolAddress((void**)&bri,  g_bri);
    cudaGetSymbolAddress((void**)&Wm1t, g_Wm1t);
    cudaGetSymbolAddress((void**)&Wm2t, g_Wm2t);

    cudaFuncSetAttribute(tgemm<5,false,false,false>, cudaFuncAttributeMaxDynamicSharedMemorySize, SMEMSZ);
    cudaFuncSetAttribute(tgemm<0,true ,true ,false>, cudaFuncAttributeMaxDynamicSharedMemorySize, SMEMSZ);
    cudaFuncSetAttribute(tgemm<0,false,true ,false>, cudaFuncAttributeMaxDynamicSharedMemorySize, SMEMSZ);
    cudaFuncSetAttribute(tgemm<4,false,false,false>, cudaFuncAttributeMaxDynamicSharedMemorySize, SMEMSZ);
    cudaFuncSetAttribute(tgemm<2,false,true ,false>, cudaFuncAttributeMaxDynamicSharedMemorySize, SMEMSZ);
    cudaFuncSetAttribute(tgemm<3,false,false,false>, cudaFuncAttributeMaxDynamicSharedMemorySize, SMEMSZ);

    dim3 g512 (DD / BN, MM / BM);          // (4, 128)
    dim3 g1024(2 * DD / BN, MM / BM);      // (8, 128)
    dim3 g2048(DM / BN, MM / BM);          // (16, 128)

    // ---- weight prep ----
    prep_weights_k<<<4608, 256>>>(W1, W2, Wm1, Wm2, pw_w, Wr, Wi,
                                  W12t, Wm1t, Wm2t, pwT, Writ);
    prep_small_k<<<2, 256>>>(br, bi, b1, b2, lam, bri, b12, lamc);
    prep_wc_k<<<256, 256>>>(dw_w, Wc);
    zero_edges_k<<<(BB * 8 * (DD/8) + 255) / 256, 256>>>(pad);

    // ---- block 1 ----
    rms_k<<<MM, 128>>>(x, g, xn);
    tgemm<5,false,false,false><<<g1024, 256, SMEMSZ>>>(xn, W12t, b12, l2, nullptr, pad, MM, 2 * DD, DD);
    tgemm<0,true ,true ,false><<<g512, 256, SMEMSZ>>>(pad, Wc, dw_b, nullptr, nullptr, conv, MM, DD, KCONV * DD);
    tgemm<0,false,true ,false><<<g512, 256, SMEMSZ>>>(conv, pwT, pw_b, nullptr, nullptr, xL, MM, DD, DD);
    tgemm<4,false,false,false><<<g1024, 256, SMEMSZ>>>(xL, Writ, bri, I, lamc, R, MM, 2 * DD, DD);
    scanA_k<<<(BB * NC * DD + 255) / 256, 256>>>(R, I, cA, cB);
    scanB_k<<<(BB * DD + 255) / 256, 256>>>(cA, cB, pref);
    scanC_k<<<(BB * NC * DD + 255) / 256, 256>>>(R, I, pref, l2, x, x1);

    // ---- block 2 (MLP) ----
    rms_k<<<MM, 128>>>(x1, g, xn2);
    tgemm<2,false,true ,false><<<g2048, 256, SMEMSZ>>>(xn2, Wm1t, bm1, nullptr, nullptr, act, MM, DM, DD);
    tgemm<3,false,false,false><<<g512, 256, SMEMSZ>>>(act, Wm2t, bm2, x1, nullptr, out, MM, DD, DM);
}

// round 12
// speedup vs baseline: 1.3304x; 1.0232x over previous
#include <cuda_runtime.h>
#include <cuda_bf16.h>
#include <math.h>

// ---------------- problem constants ----------------
#define BB    8
#define SS    2048
#define DD    512
#define MM    (BB*SS)          // 16384 rows
#define DM    (DD*4)           // 2048
#define KCONV 9
#define SPAD  (SS+8)           // 2056 padded rows per batch
#define NC    32               // scan chunks
#define LCH   (SS/NC)          // 64 steps per chunk

typedef __nv_bfloat16 bf16;
typedef __nv_bfloat162 bf162;

// ---------------- scratch (device globals; no allocs allowed) ----------------
__device__ bf16  g_xn  [MM*DD];
__device__ float g_l2  [MM*DD];
__device__ bf16  g_pad [BB*SPAD*DD];
__device__ bf16  g_conv[MM*DD];
__device__ bf16  g_xL  [MM*DD];
__device__ float g_AB  [2*MM*DD];   // interleaved scan coefficients {a,b} per (m,d)
__device__ float g_x1  [MM*DD];
__device__ bf16  g_xn2 [MM*DD];
__device__ bf16  g_act [MM*DM];
__device__ bf16  g_Wc  [KCONV*DD*DD];
__device__ bf16  g_pwT [DD*DD];
__device__ float g_cA  [BB*NC*DD];
__device__ float g_cB  [BB*NC*DD];
__device__ float g_pref[BB*NC*DD];
__device__ float g_lamc[DD];
__device__ bf16  g_W12t[DD*2*DD];   // [K=512][1024]: cols 0..511 = W1, 512..1023 = W2
__device__ float g_b12 [2*DD];
__device__ bf16  g_Writ[DD*2*DD];   // interleaved [K=512][2*512]: 2d=Wr, 2d+1=Wi
__device__ float g_bri [2*DD];
__device__ bf16  g_Wm1t[DD*DM];
__device__ bf16  g_Wm2t[DD*DM];

// ---------------- helpers ----------------
__device__ __forceinline__ float gelu_exact(float v) {
    return 0.5f * v * (1.0f + erff(v * 0.70710678118654752f));
}

__device__ __forceinline__ void mma16(float* c, const unsigned* a, const unsigned* b) {
    asm volatile(
        "mma.sync.aligned.m16n8k16.row.col.f32.bf16.bf16.f32 "
        "{%0,%1,%2,%3}, {%4,%5,%6,%7}, {%8,%9}, {%0,%1,%2,%3};"
        : "+f"(c[0]), "+f"(c[1]), "+f"(c[2]), "+f"(c[3])
        : "r"(a[0]), "r"(a[1]), "r"(a[2]), "r"(a[3]), "r"(b[0]), "r"(b[1]));
}

__device__ __forceinline__ void ldsm4(unsigned* r, unsigned addr) {
    asm volatile("ldmatrix.sync.aligned.m8n8.x4.shared.b16 {%0,%1,%2,%3}, [%4];"
                 : "=r"(r[0]), "=r"(r[1]), "=r"(r[2]), "=r"(r[3]) : "r"(addr));
}
__device__ __forceinline__ void ldsm2t(unsigned* r, unsigned addr) {
    asm volatile("ldmatrix.sync.aligned.m8n8.x2.trans.shared.b16 {%0,%1}, [%2];"
                 : "=r"(r[0]), "=r"(r[1]) : "r"(addr));
}

__device__ __forceinline__ void cpa16(unsigned s, const void* g) {
    asm volatile("cp.async.ca.shared.global [%0], [%1], 16;" :: "r"(s), "l"(g));
}
__device__ __forceinline__ void cpa_commit() {
    asm volatile("cp.async.commit_group;");
}

// ---------------- RMS norm, warp-per-row (f32 in -> bf16 out) ----------------
__global__ void rms_k(const float* __restrict__ x, const float* __restrict__ g,
                      bf16* __restrict__ o) {
    int row = blockIdx.x * 8 + (threadIdx.x >> 5);
    int lane = threadIdx.x & 31;
    const float4* xr = (const float4*)(x + (size_t)row * DD);
    float4 v[4];
    float s = 0.f;
    #pragma unroll
    for (int j = 0; j < 4; j++) {
        v[j] = xr[lane + 32 * j];
        s += v[j].x*v[j].x + v[j].y*v[j].y + v[j].z*v[j].z + v[j].w*v[j].w;
    }
    #pragma unroll
    for (int off = 16; off; off >>= 1) s += __shfl_xor_sync(0xffffffffu, s, off);
    float sc = 22.627416997969522f / (sqrtf(s) + 1e-6f);
    bf162* ob = (bf162*)(o + (size_t)row * DD);
    #pragma unroll
    for (int j = 0; j < 4; j++) {
        float4 gv = ((const float4*)g)[lane + 32 * j];
        int idx = 2 * (lane + 32 * j);
        ob[idx]     = __floats2bfloat162_rn(v[j].x * sc * gv.x, v[j].y * sc * gv.y);
        ob[idx + 1] = __floats2bfloat162_rn(v[j].z * sc * gv.z, v[j].w * sc * gv.w);
    }
}

// ---------------- bf16 tensor-core GEMM, 128x128 tile (round-8 proven config) ----------------
// EPI: 0 = bias, 2 = gelu(v)*v, 3 = +res, 4 = fused RG-LRU gates -> float2 {a,b},
//      5 = dual W1/W2 (cols<512 -> bf16 pad w/ remap, cols>=512 -> f32 l2)
// CONV: A read from padded activations with tap offsets (K'=9*512)
// OUTBF: output bf16, else f32. PADOUT: padded-row output remap.
#define BM 128
#define BN 128
#define BK 32
#define APITCH 40      // 80B rows, conflict-free ldsm
#define BPITCH 136     // 272B rows
#define NSTG 3
#define SMEMSZ (NSTG*(BM*APITCH + BK*BPITCH)*2)

template <int EPI, bool CONV, bool OUTBF, bool PADOUT>
__global__ void __launch_bounds__(256, 2)
tgemm(const bf16* __restrict__ A, const bf16* __restrict__ Bw,
      const float* __restrict__ bias, float* __restrict__ res,
      const float* __restrict__ lamc, void* __restrict__ Cv,
      int M_, int N_, int K_) {
    extern __shared__ bf16 smb[];
    bf16 (*As)[BM][APITCH] = (bf16(*)[BM][APITCH])smb;
    bf16 (*Bs)[BK][BPITCH] = (bf16(*)[BK][BPITCH])(smb + NSTG * BM * APITCH);

    const int tid = threadIdx.x;
    const int m0 = blockIdx.y * BM;
    const int n0 = blockIdx.x * BN;
    const int warp = tid >> 5, lane = tid & 31;
    const int wm = (warp >> 2) * 64;
    const int wn = (warp & 3) * 32;
    const int padbase = CONV ? (m0 + 8 * (m0 / SS)) : 0;

    // cp.async staging
    const int arow = tid >> 1;          // 0..127
    const int acol = (tid & 1) * 16;    // 0 or 16
    const int brow = tid >> 3;          // 0..31
    const int bcol = (tid & 7) * 16;    // 0..112

    // ldmatrix lane offsets
    const int a_rowoff = (lane & 7) + ((lane >> 3) & 1) * 8;
    const int a_coloff = (lane >> 4) * 8;
    const int b_rowoff = lane & 15;

    const unsigned sA = (unsigned)__cvta_generic_to_shared(smb);
    const unsigned sB = (unsigned)__cvta_generic_to_shared(smb + NSTG * BM * APITCH);
    const unsigned aBase = sA + (unsigned)(((wm + a_rowoff) * APITCH + a_coloff) * 2);
    const unsigned bBase = sB + (unsigned)((b_rowoff * BPITCH + wn) * 2);

    const int nit = K_ / BK;

    auto prefetch = [&](int it, int buf) {
        int k0 = it * BK;
        const bf16* ga;
        if (CONV) {
            int tap = k0 >> 9;
            int kin = k0 & 511;
            ga = A + (size_t)(padbase + arow + tap) * DD + kin + acol;
        } else {
            ga = A + (size_t)(m0 + arow) * K_ + k0 + acol;
        }
        unsigned da = (unsigned)__cvta_generic_to_shared(&As[buf][arow][acol]);
        cpa16(da, ga);
        cpa16(da + 16, ga + 8);
        const bf16* gb = Bw + (size_t)(k0 + brow) * N_ + n0 + bcol;
        unsigned db = (unsigned)__cvta_generic_to_shared(&Bs[buf][brow][bcol]);
        cpa16(db, gb);
        cpa16(db + 16, gb + 8);
    };

    float acc[4][4][4] = {};

    prefetch(0, 0); cpa_commit();
    if (nit > 1) { prefetch(1, 1); cpa_commit(); }

    for (int it = 0; it < nit; it++) {
        if (it + 1 < nit) asm volatile("cp.async.wait_group 1;");
        else              asm volatile("cp.async.wait_group 0;");
        __syncthreads();
        if (it + 2 < nit) { prefetch(it + 2, (it + 2) % NSTG); cpa_commit(); }

        const int buf = it % NSTG;
        const unsigned ab = aBase + (unsigned)(buf * BM * APITCH * 2);
        const unsigned bb = bBase + (unsigned)(buf * BK * BPITCH * 2);
        #pragma unroll
        for (int t = 0; t < 2; t++) {
            unsigned af[4][4], bfr[4][2];
            #pragma unroll
            for (int mi = 0; mi < 4; mi++)
                ldsm4(af[mi], ab + (unsigned)((mi * 16 * APITCH + 16 * t) * 2));
            #pragma unroll
            for (int ni = 0; ni < 4; ni++)
                ldsm2t(bfr[ni], bb + (unsigned)((16 * t * BPITCH + 8 * ni) * 2));
            #pragma unroll
            for (int mi = 0; mi < 4; mi++)
                #pragma unroll
                for (int ni = 0; ni < 4; ni++)
                    mma16(acc[mi][ni], af[mi], bfr[ni]);
        }
        // single barrier per iteration is sufficient with NSTG=3
    }

    // epilogue
    const int r = lane >> 2, cg = lane & 3;
    const int opitch = PADOUT ? DD : N_;
    #pragma unroll
    for (int mi = 0; mi < 4; mi++) {
        int mlo = m0 + wm + mi * 16 + r;
        int mhi = mlo + 8;
        int olo = PADOUT ? (mlo + 4 + 8 * (mlo >> 11)) : mlo;
        int ohi = PADOUT ? (mhi + 4 + 8 * (mhi >> 11)) : mhi;
        #pragma unroll
        for (int ni = 0; ni < 4; ni++) {
            int n = n0 + wn + ni * 8 + 2 * cg;
            float b0 = bias[n], b1 = bias[n + 1];
            float v0 = acc[mi][ni][0] + b0;
            float v1 = acc[mi][ni][1] + b1;
            float v2 = acc[mi][ni][2] + b0;
            float v3 = acc[mi][ni][3] + b1;
            if (EPI == 4) {
                int d = n >> 1;
                float lc = lamc[d];
                float r0 = 1.f / (1.f + __expf(-v0));
                float i0 = 1.f / (1.f + __expf(-v1));
                float r1 = 1.f / (1.f + __expf(-v2));
                float i1 = 1.f / (1.f + __expf(-v3));
                float a0 = __expf(lc * r0), a1 = __expf(lc * r1);
                float xl0 = __bfloat162float(A[(size_t)mlo * DD + d]);
                float xl1 = __bfloat162float(A[(size_t)mhi * DD + d]);
                float bb0 = sqrtf(fmaxf(0.f, 1.f - a0 * a0)) * i0 * xl0;
                float bb1 = sqrtf(fmaxf(0.f, 1.f - a1 * a1)) * i1 * xl1;
                float2* ABp = (float2*)Cv;
                ABp[(size_t)mlo * DD + d] = make_float2(a0, bb0);
                ABp[(size_t)mhi * DD + d] = make_float2(a1, bb1);
                continue;
            }
            if (EPI == 5) {
                if (n0 < DD) {
                    bf16* C = (bf16*)Cv;
                    int plo = mlo + 4 + 8 * (mlo >> 11);
                    int phi = mhi + 4 + 8 * (mhi >> 11);
                    *(bf162*)(C + (size_t)plo * DD + n) = __floats2bfloat162_rn(v0, v1);
                    *(bf162*)(C + (size_t)phi * DD + n) = __floats2bfloat162_rn(v2, v3);
                } else {
                    int c = n - DD;
                    *(float2*)(res + (size_t)mlo * DD + c) = make_float2(v0, v1);
                    *(float2*)(res + (size_t)mhi * DD + c) = make_float2(v2, v3);
                }
                continue;
            }
            if (EPI == 2) {
                v0 *= gelu_exact(v0); v1 *= gelu_exact(v1);
                v2 *= gelu_exact(v2); v3 *= gelu_exact(v3);
            } else if (EPI == 3) {
                float2 r0 = *(const float2*)(res + (size_t)mlo * N_ + n);
                float2 r1 = *(const float2*)(res + (size_t)mhi * N_ + n);
                v0 += r0.x; v1 += r0.y; v2 += r1.x; v3 += r1.y;
            }
            if (OUTBF) {
                bf16* C = (bf16*)Cv;
                *(bf162*)(C + (size_t)olo * opitch + n) = __floats2bfloat162_rn(v0, v1);
                *(bf162*)(C + (size_t)ohi * opitch + n) = __floats2bfloat162_rn(v2, v3);
            } else {
                float* C = (float*)Cv;
                *(float2*)(C + (size_t)olo * opitch + n) = make_float2(v0, v1);
                *(float2*)(C + (size_t)ohi * opitch + n) = make_float2(v2, v3);
            }
        }
    }
}

// ---------------- weight prep (merged, ranged dispatch) ----------------
__global__ void prep_weights_k(const float* __restrict__ W1, const float* __restrict__ W2,
                               const float* __restrict__ Wm1, const float* __restrict__ Wm2,
                               const float* __restrict__ pw_w,
                               const float* __restrict__ Wr, const float* __restrict__ Wi,
                               bf16* __restrict__ W12t, bf16* __restrict__ Wm1t,
                               bf16* __restrict__ Wm2t, bf16* __restrict__ pwT,
                               bf16* __restrict__ Writ) {
    int b = blockIdx.x, tid = threadIdx.x;
    if (b < 512) {
        const float* s = (b < 256) ? W1 : W2;
        int coff = (b < 256) ? 0 : DD;
        int i = ((b & 255) * 256 + tid);            // float4 index, 65536 total
        float4 v = ((const float4*)s)[i];
        int k = i >> 7;
        int c = (i & 127) * 4 + coff;
        bf162* d = (bf162*)(W12t + (size_t)k * (2 * DD) + c);
        d[0] = __floats2bfloat162_rn(v.x, v.y);
        d[1] = __floats2bfloat162_rn(v.z, v.w);
        return;
    }
    if (b < 2560) {
        const float* s = (b < 1536) ? Wm1 : Wm2;
        bf16* d = (b < 1536) ? Wm1t : Wm2t;
        int j = ((b < 1536) ? (b - 512) : (b - 1536)) * 256 + tid;  // float4 idx, 262144
        float4 v = ((const float4*)s)[j];
        ((bf162*)d)[2*j]   = __floats2bfloat162_rn(v.x, v.y);
        ((bf162*)d)[2*j+1] = __floats2bfloat162_rn(v.z, v.w);
        return;
    }
    if (b < 3584) {
        int idx = (b - 2560) * 256 + tid;           // 262144 elements
        int o = idx % DD;
        int i = idx / DD;
        pwT[idx] = __float2bfloat16(pw_w[(size_t)o * DD + i]);
        return;
    }
    {
        int idx = (b - 3584) * 256 + tid;           // 262144 elements
        int k = idx / DD, d = idx % DD;
        Writ[(size_t)k * (2 * DD) + 2 * d]     = __float2bfloat16(Wr[idx]);
        Writ[(size_t)k * (2 * DD) + 2 * d + 1] = __float2bfloat16(Wi[idx]);
    }
}

// small vectors + pad-halo zeroing, ranged dispatch:
// blocks 0..1 : bri/b12/lamc ; blocks 2..17 : zero pad edges
__global__ void prep_small_k(const float* __restrict__ br, const float* __restrict__ bi,
                             const float* __restrict__ b1, const float* __restrict__ b2,
                             const float* __restrict__ lam,
                             float* __restrict__ bri, float* __restrict__ b12,
                             float* __restrict__ lamc, bf16* __restrict__ pad) {
    int b = blockIdx.x, tid = threadIdx.x;
    if (b < 2) {
        int d = b * 256 + tid;
        bri[2 * d]     = br[d];
        bri[2 * d + 1] = bi[d];
        b12[d]        = b1[d];
        b12[DD + d]   = b2[d];
        float l = lam[d];
        float sp = (l > 15.f) ? l : log1pf(expf(l));
        lamc[d] = -8.0f * sp;
        return;
    }
    int idx = (b - 2) * 256 + tid;      // 4096 chunks of 8 bf16
    int c = idx & 63;
    int rr = idx >> 6;
    int bb = rr >> 3, j = rr & 7;
    int p = (j < 4) ? j : (2048 + j);
    uint4 z = make_uint4(0, 0, 0, 0);
    *(uint4*)(pad + ((size_t)bb * SPAD + p) * DD + c * 8) = z;
}

// transpose dw_w (o,i,k) -> Wc[k][i][o] via smem tiles (row 9: 2-way max conflicts)
__global__ void prep_wc_k(const float* __restrict__ dw_w, bf16* __restrict__ Wc) {
    __shared__ bf16 s[1024][9];    // [o_local*32 + i_local][k]
    int o0 = (blockIdx.x & 15) * 32;
    int i0 = (blockIdx.x >> 4) * 32;
    int t = threadIdx.x;           // 256 threads
    for (int p = t; p < 1024; p += 256) {
        int ol = p >> 5, il = p & 31;
        const float* src = dw_w + ((size_t)(o0 + ol) * DD + (i0 + il)) * KCONV;
        #pragma unroll
        for (int k = 0; k < KCONV; k++) s[p][k] = __float2bfloat16(src[k]);
    }
    __syncthreads();
    #pragma unroll
    for (int k = 0; k < KCONV; k++) {
        for (int e = t; e < 1024; e += 256) {
            int il = e >> 5, ol = e & 31;
            Wc[(size_t)k * DD * DD + (size_t)(i0 + il) * DD + (o0 + ol)] = s[ol * 32 + il][k];
        }
    }
}

// ---------------- chunked linear scan (interleaved {a,b} coefficients) ----------------
__global__ void scanA_k(const float2* __restrict__ AB,
                        float* __restrict__ cA, float* __restrict__ cB) {
    int t = blockIdx.x * blockDim.x + threadIdx.x;
    if (t >= BB * NC * DD) return;
    int d = t & (DD - 1);
    int chunk = (t >> 9) & (NC - 1);
    int batch = t >> 14;
    size_t base = ((size_t)batch * SS + (size_t)chunk * LCH) * DD + d;
    float A = 1.f, Bv = 0.f;
    for (int s = 0; s < LCH; s++) {
        float2 ab = AB[base + (size_t)s * DD];
        Bv = ab.x * Bv + ab.y;
        A *= ab.x;
    }
    cA[t] = A; cB[t] = Bv;
}

__global__ void scanB_k(const float* __restrict__ cA, const float* __restrict__ cB,
                        float* __restrict__ pref) {
    int t = blockIdx.x * blockDim.x + threadIdx.x;
    if (t >= BB * DD) return;
    int d = t & (DD - 1);
    int batch = t >> 9;
    float h = 0.f;
    for (int c = 0; c < NC; c++) {
        size_t idx = ((size_t)batch * NC + c) * DD + d;
        pref[idx] = h;
        h = cA[idx] * h + cB[idx];
    }
}

__global__ void scanC_k(const float2* __restrict__ AB,
                        const float* __restrict__ pref, const float* __restrict__ l2,
                        const float* __restrict__ skip, float* __restrict__ x1) {
    int t = blockIdx.x * blockDim.x + threadIdx.x;
    if (t >= BB * NC * DD) return;
    int d = t & (DD - 1);
    int chunk = (t >> 9) & (NC - 1);
    int batch = t >> 14;
    size_t base = ((size_t)batch * SS + (size_t)chunk * LCH) * DD + d;
    float h = pref[t];
    for (int s = 0; s < LCH; s++) {
        size_t idx = base + (size_t)s * DD;
        float2 ab = AB[idx];
        h = ab.x * h + ab.y;
        x1[idx] = h * gelu_exact(l2[idx]) + skip[idx];
    }
}

// ---------------- launch ----------------
extern "C" void kernel_launch(void* const* d_in, const int* in_sizes, int n_in,
                              void* d_out, int out_size) {
    const float* x    = (const float*)d_in[0];
    const float* g    = (const float*)d_in[1];
    const float* W1   = (const float*)d_in[2];
    const float* b1   = (const float*)d_in[3];
    const float* W2   = (const float*)d_in[4];
    const float* b2   = (const float*)d_in[5];
    const float* dw_w = (const float*)d_in[6];
    const float* dw_b = (const float*)d_in[7];
    const float* pw_w = (const float*)d_in[8];
    const float* pw_b = (const float*)d_in[9];
    const float* Wi   = (const float*)d_in[10];
    const float* bi   = (const float*)d_in[11];
    const float* Wr   = (const float*)d_in[12];
    const float* br   = (const float*)d_in[13];
    const float* lam  = (const float*)d_in[14];
    const float* Wm1  = (const float*)d_in[15];
    const float* bm1  = (const float*)d_in[16];
    const float* Wm2  = (const float*)d_in[17];
    const float* bm2  = (const float*)d_in[18];
    float* out = (float*)d_out;

    bf16 *xn, *pad, *conv, *xL, *xn2, *act, *Wc, *pwT;
    bf16 *W12t, *Writ, *Wm1t, *Wm2t;
    float *l2, *AB, *x1, *cA, *cB, *pref, *lamc, *bri, *b12;
    cudaGetSymbolAddress((void**)&xn,   g_xn);
    cudaGetSymbolAddress((void**)&l2,   g_l2);
    cudaGetSymbolAddress((void**)&pad,  g_pad);
    cudaGetSymbolAddress((void**)&conv, g_conv);
    cudaGetSymbolAddress((void**)&xL,   g_xL);
    cudaGetSymbolAddress((void**)&AB,   g_AB);
    cudaGetSymbolAddress((void**)&x1,   g_x1);
    cudaGetSymbolAddress((void**)&xn2,  g_xn2);
    cudaGetSymbolAddress((void**)&act,  g_act);
    cudaGetSymbolAddress((void**)&Wc,   g_Wc);
    cudaGetSymbolAddress((void**)&pwT,  g_pwT);
    cudaGetSymbolAddress((void**)&cA,   g_cA);
    cudaGetSymbolAddress((void**)&cB,   g_cB);
    cudaGetSymbolAddress((void**)&pref, g_pref);
    cudaGetSymbolAddress((void**)&lamc, g_lamc);
    cudaGetSymbolAddress((void**)&W12t, g_W12t);
    cudaGetSymbolAddress((void**)&b12,  g_b12);
    cudaGetSymbolAddress((void**)&Writ, g_Writ);
    cudaGetSymbolAddress((void**)&bri,  g_bri);
    cudaGetSymbolAddress((void**)&Wm1t, g_Wm1t);
    cudaGetSymbolAddress((void**)&Wm2t, g_Wm2t);

    cudaFuncSetAttribute(tgemm<5,false,false,false>, cudaFuncAttributeMaxDynamicSharedMemorySize, SMEMSZ);
    cudaFuncSetAttribute(tgemm<0,true ,true ,false>, cudaFuncAttributeMaxDynamicSharedMemorySize, SMEMSZ);
    cudaFuncSetAttribute(tgemm<0,false,true ,false>, cudaFuncAttributeMaxDynamicSharedMemorySize, SMEMSZ);
    cudaFuncSetAttribute(tgemm<4,false,false,false>, cudaFuncAttributeMaxDynamicSharedMemorySize, SMEMSZ);
    cudaFuncSetAttribute(tgemm<2,false,true ,false>, cudaFuncAttributeMaxDynamicSharedMemorySize, SMEMSZ);
    cudaFuncSetAttribute(tgemm<3,false,false,false>, cudaFuncAttributeMaxDynamicSharedMemorySize, SMEMSZ);

    dim3 g512 (DD / BN, MM / BM);          // (4, 128)
    dim3 g1024(2 * DD / BN, MM / BM);      // (8, 128)
    dim3 g2048(DM / BN, MM / BM);          // (16, 128)

    // ---- weight prep ----
    prep_weights_k<<<4608, 256>>>(W1, W2, Wm1, Wm2, pw_w, Wr, Wi,
                                  W12t, Wm1t, Wm2t, pwT, Writ);
    prep_small_k<<<18, 256>>>(br, bi, b1, b2, lam, bri, b12, lamc, pad);
    prep_wc_k<<<256, 256>>>(dw_w, Wc);

    // ---- block 1 ----
    rms_k<<<MM / 8, 256>>>(x, g, xn);
    tgemm<5,false,false,false><<<g1024, 256, SMEMSZ>>>(xn, W12t, b12, l2, nullptr, pad, MM, 2 * DD, DD);
    tgemm<0,true ,true ,false><<<g512, 256, SMEMSZ>>>(pad, Wc, dw_b, nullptr, nullptr, conv, MM, DD, KCONV * DD);
    tgemm<0,false,true ,false><<<g512, 256, SMEMSZ>>>(conv, pwT, pw_b, nullptr, nullptr, xL, MM, DD, DD);
    tgemm<4,false,false,false><<<g1024, 256, SMEMSZ>>>(xL, Writ, bri, nullptr, lamc, AB, MM, 2 * DD, DD);
    scanA_k<<<(BB * NC * DD + 255) / 256, 256>>>((const float2*)AB, cA, cB);
    scanB_k<<<(BB * DD + 255) / 256, 256>>>(cA, cB, pref);
    scanC_k<<<(BB * NC * DD + 255) / 256, 256>>>((const float2*)AB, pref, l2, x, x1);

    // ---- block 2 (MLP) ----
    rms_k<<<MM / 8, 256>>>(x1, g, xn2);
    tgemm<2,false,true ,false><<<g2048, 256, SMEMSZ>>>(xn2, Wm1t, bm1, nullptr, nullptr, act, MM, DM, DD);
    tgemm<3,false,false,false><<<g512, 256, SMEMSZ>>>(act, Wm2t, bm2, x1, nullptr, out, MM, DD, DM);
}

// round 13
// speedup vs baseline: 1.3426x; 1.0092x over previous
#include <cuda_runtime.h>
#include <cuda_bf16.h>
#include <math.h>

// ---------------- problem constants ----------------
#define BB    8
#define SS    2048
#define DD    512
#define MM    (BB*SS)          // 16384 rows
#define DM    (DD*4)           // 2048
#define KCONV 9
#define SPAD  (SS+8)           // 2056 padded rows per batch
#define NC    32               // scan chunks
#define LCH   (SS/NC)          // 64 steps per chunk

typedef __nv_bfloat16 bf16;
typedef __nv_bfloat162 bf162;

// ---------------- scratch (device globals; no allocs allowed) ----------------
__device__ bf16  g_xn  [MM*DD];
__device__ float g_l2  [MM*DD];
__device__ bf16  g_pad [BB*SPAD*DD];
__device__ bf16  g_conv[MM*DD];
__device__ bf16  g_xL  [MM*DD];
__device__ float g_AB  [2*MM*DD];   // interleaved scan coefficients {a,b} per (m,d)
__device__ float g_x1  [MM*DD];
__device__ bf16  g_xn2 [MM*DD];
__device__ bf16  g_act [MM*DM];
__device__ bf16  g_Wc  [KCONV*DD*DD];
__device__ bf16  g_pwT [DD*DD];
__device__ float g_lamc[DD];
__device__ bf16  g_W12t[DD*2*DD];   // [K=512][1024]: cols 0..511 = W1, 512..1023 = W2
__device__ float g_b12 [2*DD];
__device__ bf16  g_Writ[DD*2*DD];   // interleaved [K=512][2*512]: 2d=Wr, 2d+1=Wi
__device__ float g_bri [2*DD];
__device__ bf16  g_Wm1t[DD*DM];
__device__ bf16  g_Wm2t[DD*DM];

// ---------------- helpers ----------------
__device__ __forceinline__ float gelu_exact(float v) {
    return 0.5f * v * (1.0f + erff(v * 0.70710678118654752f));
}

__device__ __forceinline__ void mma16(float* c, const unsigned* a, const unsigned* b) {
    asm volatile(
        "mma.sync.aligned.m16n8k16.row.col.f32.bf16.bf16.f32 "
        "{%0,%1,%2,%3}, {%4,%5,%6,%7}, {%8,%9}, {%0,%1,%2,%3};"
        : "+f"(c[0]), "+f"(c[1]), "+f"(c[2]), "+f"(c[3])
        : "r"(a[0]), "r"(a[1]), "r"(a[2]), "r"(a[3]), "r"(b[0]), "r"(b[1]));
}

__device__ __forceinline__ void ldsm4(unsigned* r, unsigned addr) {
    asm volatile("ldmatrix.sync.aligned.m8n8.x4.shared.b16 {%0,%1,%2,%3}, [%4];"
                 : "=r"(r[0]), "=r"(r[1]), "=r"(r[2]), "=r"(r[3]) : "r"(addr));
}
__device__ __forceinline__ void ldsm2t(unsigned* r, unsigned addr) {
    asm volatile("ldmatrix.sync.aligned.m8n8.x2.trans.shared.b16 {%0,%1}, [%2];"
                 : "=r"(r[0]), "=r"(r[1]) : "r"(addr));
}

__device__ __forceinline__ void cpa16(unsigned s, const void* g) {
    asm volatile("cp.async.ca.shared.global [%0], [%1], 16;" :: "r"(s), "l"(g));
}
__device__ __forceinline__ void cpa_commit() {
    asm volatile("cp.async.commit_group;");
}

// ---------------- RMS norm, warp-per-row (f32 in -> bf16 out) ----------------
__global__ void rms_k(const float* __restrict__ x, const float* __restrict__ g,
                      bf16* __restrict__ o) {
    int row = blockIdx.x * 8 + (threadIdx.x >> 5);
    int lane = threadIdx.x & 31;
    const float4* xr = (const float4*)(x + (size_t)row * DD);
    float4 v[4];
    float s = 0.f;
    #pragma unroll
    for (int j = 0; j < 4; j++) {
        v[j] = xr[lane + 32 * j];
        s += v[j].x*v[j].x + v[j].y*v[j].y + v[j].z*v[j].z + v[j].w*v[j].w;
    }
    #pragma unroll
    for (int off = 16; off; off >>= 1) s += __shfl_xor_sync(0xffffffffu, s, off);
    float sc = 22.627416997969522f / (sqrtf(s) + 1e-6f);
    bf162* ob = (bf162*)(o + (size_t)row * DD);
    #pragma unroll
    for (int j = 0; j < 4; j++) {
        float4 gv = ((const float4*)g)[lane + 32 * j];
        int idx = 2 * (lane + 32 * j);
        ob[idx]     = __floats2bfloat162_rn(v[j].x * sc * gv.x, v[j].y * sc * gv.y);
        ob[idx + 1] = __floats2bfloat162_rn(v[j].z * sc * gv.z, v[j].w * sc * gv.w);
    }
}

// ---------------- bf16 tensor-core GEMM, 128x128 tile (round-8 proven config) ----------------
// EPI: 0 = bias, 2 = gelu(v)*v, 3 = +res, 4 = fused RG-LRU gates -> float2 {a,b},
//      5 = dual W1/W2 (cols<512 -> bf16 pad w/ remap, cols>=512 -> f32 l2)
// CONV: A read from padded activations with tap offsets (K'=9*512)
// OUTBF: output bf16, else f32. PADOUT: padded-row output remap.
#define BM 128
#define BN 128
#define BK 32
#define APITCH 40      // 80B rows, conflict-free ldsm
#define BPITCH 136     // 272B rows
#define NSTG 3
#define SMEMSZ (NSTG*(BM*APITCH + BK*BPITCH)*2)

template <int EPI, bool CONV, bool OUTBF, bool PADOUT>
__global__ void __launch_bounds__(256, 2)
tgemm(const bf16* __restrict__ A, const bf16* __restrict__ Bw,
      const float* __restrict__ bias, float* __restrict__ res,
      const float* __restrict__ lamc, void* __restrict__ Cv,
      int M_, int N_, int K_) {
    extern __shared__ bf16 smb[];
    bf16 (*As)[BM][APITCH] = (bf16(*)[BM][APITCH])smb;
    bf16 (*Bs)[BK][BPITCH] = (bf16(*)[BK][BPITCH])(smb + NSTG * BM * APITCH);

    const int tid = threadIdx.x;
    const int m0 = blockIdx.y * BM;
    const int n0 = blockIdx.x * BN;
    const int warp = tid >> 5, lane = tid & 31;
    const int wm = (warp >> 2) * 64;
    const int wn = (warp & 3) * 32;
    const int padbase = CONV ? (m0 + 8 * (m0 / SS)) : 0;

    // cp.async staging
    const int arow = tid >> 1;          // 0..127
    const int acol = (tid & 1) * 16;    // 0 or 16
    const int brow = tid >> 3;          // 0..31
    const int bcol = (tid & 7) * 16;    // 0..112

    // ldmatrix lane offsets
    const int a_rowoff = (lane & 7) + ((lane >> 3) & 1) * 8;
    const int a_coloff = (lane >> 4) * 8;
    const int b_rowoff = lane & 15;

    const unsigned sA = (unsigned)__cvta_generic_to_shared(smb);
    const unsigned sB = (unsigned)__cvta_generic_to_shared(smb + NSTG * BM * APITCH);
    const unsigned aBase = sA + (unsigned)(((wm + a_rowoff) * APITCH + a_coloff) * 2);
    const unsigned bBase = sB + (unsigned)((b_rowoff * BPITCH + wn) * 2);

    const int nit = K_ / BK;

    auto prefetch = [&](int it, int buf) {
        int k0 = it * BK;
        const bf16* ga;
        if (CONV) {
            int tap = k0 >> 9;
            int kin = k0 & 511;
            ga = A + (size_t)(padbase + arow + tap) * DD + kin + acol;
        } else {
            ga = A + (size_t)(m0 + arow) * K_ + k0 + acol;
        }
        unsigned da = (unsigned)__cvta_generic_to_shared(&As[buf][arow][acol]);
        cpa16(da, ga);
        cpa16(da + 16, ga + 8);
        const bf16* gb = Bw + (size_t)(k0 + brow) * N_ + n0 + bcol;
        unsigned db = (unsigned)__cvta_generic_to_shared(&Bs[buf][brow][bcol]);
        cpa16(db, gb);
        cpa16(db + 16, gb + 8);
    };

    float acc[4][4][4] = {};

    prefetch(0, 0); cpa_commit();
    if (nit > 1) { prefetch(1, 1); cpa_commit(); }

    for (int it = 0; it < nit; it++) {
        if (it + 1 < nit) asm volatile("cp.async.wait_group 1;");
        else              asm volatile("cp.async.wait_group 0;");
        __syncthreads();
        if (it + 2 < nit) { prefetch(it + 2, (it + 2) % NSTG); cpa_commit(); }

        const int buf = it % NSTG;
        const unsigned ab = aBase + (unsigned)(buf * BM * APITCH * 2);
        const unsigned bb = bBase + (unsigned)(buf * BK * BPITCH * 2);
        #pragma unroll
        for (int t = 0; t < 2; t++) {
            unsigned af[4][4], bfr[4][2];
            #pragma unroll
            for (int mi = 0; mi < 4; mi++)
                ldsm4(af[mi], ab + (unsigned)((mi * 16 * APITCH + 16 * t) * 2));
            #pragma unroll
            for (int ni = 0; ni < 4; ni++)
                ldsm2t(bfr[ni], bb + (unsigned)((16 * t * BPITCH + 8 * ni) * 2));
            #pragma unroll
            for (int mi = 0; mi < 4; mi++)
                #pragma unroll
                for (int ni = 0; ni < 4; ni++)
                    mma16(acc[mi][ni], af[mi], bfr[ni]);
        }
        // single barrier per iteration is sufficient with NSTG=3
    }

    // epilogue
    const int r = lane >> 2, cg = lane & 3;
    const int opitch = PADOUT ? DD : N_;
    #pragma unroll
    for (int mi = 0; mi < 4; mi++) {
        int mlo = m0 + wm + mi * 16 + r;
        int mhi = mlo + 8;
        int olo = PADOUT ? (mlo + 4 + 8 * (mlo >> 11)) : mlo;
        int ohi = PADOUT ? (mhi + 4 + 8 * (mhi >> 11)) : mhi;
        #pragma unroll
        for (int ni = 0; ni < 4; ni++) {
            int n = n0 + wn + ni * 8 + 2 * cg;
            float b0 = bias[n], b1 = bias[n + 1];
            float v0 = acc[mi][ni][0] + b0;
            float v1 = acc[mi][ni][1] + b1;
            float v2 = acc[mi][ni][2] + b0;
            float v3 = acc[mi][ni][3] + b1;
            if (EPI == 4) {
                int d = n >> 1;
                float lc = lamc[d];
                float r0 = 1.f / (1.f + __expf(-v0));
                float i0 = 1.f / (1.f + __expf(-v1));
                float r1 = 1.f / (1.f + __expf(-v2));
                float i1 = 1.f / (1.f + __expf(-v3));
                float a0 = __expf(lc * r0), a1 = __expf(lc * r1);
                float xl0 = __bfloat162float(A[(size_t)mlo * DD + d]);
                float xl1 = __bfloat162float(A[(size_t)mhi * DD + d]);
                float bb0 = sqrtf(fmaxf(0.f, 1.f - a0 * a0)) * i0 * xl0;
                float bb1 = sqrtf(fmaxf(0.f, 1.f - a1 * a1)) * i1 * xl1;
                float2* ABp = (float2*)Cv;
                ABp[(size_t)mlo * DD + d] = make_float2(a0, bb0);
                ABp[(size_t)mhi * DD + d] = make_float2(a1, bb1);
                continue;
            }
            if (EPI == 5) {
                if (n0 < DD) {
                    bf16* C = (bf16*)Cv;
                    int plo = mlo + 4 + 8 * (mlo >> 11);
                    int phi = mhi + 4 + 8 * (mhi >> 11);
                    *(bf162*)(C + (size_t)plo * DD + n) = __floats2bfloat162_rn(v0, v1);
                    *(bf162*)(C + (size_t)phi * DD + n) = __floats2bfloat162_rn(v2, v3);
                } else {
                    int c = n - DD;
                    *(float2*)(res + (size_t)mlo * DD + c) = make_float2(v0, v1);
                    *(float2*)(res + (size_t)mhi * DD + c) = make_float2(v2, v3);
                }
                continue;
            }
            if (EPI == 2) {
                v0 *= gelu_exact(v0); v1 *= gelu_exact(v1);
                v2 *= gelu_exact(v2); v3 *= gelu_exact(v3);
            } else if (EPI == 3) {
                float2 r0 = *(const float2*)(res + (size_t)mlo * N_ + n);
                float2 r1 = *(const float2*)(res + (size_t)mhi * N_ + n);
                v0 += r0.x; v1 += r0.y; v2 += r1.x; v3 += r1.y;
            }
            if (OUTBF) {
                bf16* C = (bf16*)Cv;
                *(bf162*)(C + (size_t)olo * opitch + n) = __floats2bfloat162_rn(v0, v1);
                *(bf162*)(C + (size_t)ohi * opitch + n) = __floats2bfloat162_rn(v2, v3);
            } else {
                float* C = (float*)Cv;
                *(float2*)(C + (size_t)olo * opitch + n) = make_float2(v0, v1);
                *(float2*)(C + (size_t)ohi * opitch + n) = make_float2(v2, v3);
            }
        }
    }
}

// ---------------- weight prep (merged, ranged dispatch) ----------------
__global__ void prep_weights_k(const float* __restrict__ W1, const float* __restrict__ W2,
                               const float* __restrict__ Wm1, const float* __restrict__ Wm2,
                               const float* __restrict__ pw_w,
                               const float* __restrict__ Wr, const float* __restrict__ Wi,
                               bf16* __restrict__ W12t, bf16* __restrict__ Wm1t,
                               bf16* __restrict__ Wm2t, bf16* __restrict__ pwT,
                               bf16* __restrict__ Writ) {
    int b = blockIdx.x, tid = threadIdx.x;
    if (b < 512) {
        const float* s = (b < 256) ? W1 : W2;
        int coff = (b < 256) ? 0 : DD;
        int i = ((b & 255) * 256 + tid);            // float4 index, 65536 total
        float4 v = ((const float4*)s)[i];
        int k = i >> 7;
        int c = (i & 127) * 4 + coff;
        bf162* d = (bf162*)(W12t + (size_t)k * (2 * DD) + c);
        d[0] = __floats2bfloat162_rn(v.x, v.y);
        d[1] = __floats2bfloat162_rn(v.z, v.w);
        return;
    }
    if (b < 2560) {
        const float* s = (b < 1536) ? Wm1 : Wm2;
        bf16* d = (b < 1536) ? Wm1t : Wm2t;
        int j = ((b < 1536) ? (b - 512) : (b - 1536)) * 256 + tid;  // float4 idx, 262144
        float4 v = ((const float4*)s)[j];
        ((bf162*)d)[2*j]   = __floats2bfloat162_rn(v.x, v.y);
        ((bf162*)d)[2*j+1] = __floats2bfloat162_rn(v.z, v.w);
        return;
    }
    if (b < 3584) {
        int idx = (b - 2560) * 256 + tid;           // 262144 elements
        int o = idx % DD;
        int i = idx / DD;
        pwT[idx] = __float2bfloat16(pw_w[(size_t)o * DD + i]);
        return;
    }
    {
        int idx = (b - 3584) * 256 + tid;           // 262144 elements
        int k = idx / DD, d = idx % DD;
        Writ[(size_t)k * (2 * DD) + 2 * d]     = __float2bfloat16(Wr[idx]);
        Writ[(size_t)k * (2 * DD) + 2 * d + 1] = __float2bfloat16(Wi[idx]);
    }
}

// small vectors + pad-halo zeroing, ranged dispatch:
// blocks 0..1 : bri/b12/lamc ; blocks 2..17 : zero pad edges
__global__ void prep_small_k(const float* __restrict__ br, const float* __restrict__ bi,
                             const float* __restrict__ b1, const float* __restrict__ b2,
                             const float* __restrict__ lam,
                             float* __restrict__ bri, float* __restrict__ b12,
                             float* __restrict__ lamc, bf16* __restrict__ pad) {
    int b = blockIdx.x, tid = threadIdx.x;
    if (b < 2) {
        int d = b * 256 + tid;
        bri[2 * d]     = br[d];
        bri[2 * d + 1] = bi[d];
        b12[d]        = b1[d];
        b12[DD + d]   = b2[d];
        float l = lam[d];
        float sp = (l > 15.f) ? l : log1pf(expf(l));
        lamc[d] = -8.0f * sp;
        return;
    }
    int idx = (b - 2) * 256 + tid;      // 4096 chunks of 8 bf16
    int c = idx & 63;
    int rr = idx >> 6;
    int bb = rr >> 3, j = rr & 7;
    int p = (j < 4) ? j : (2048 + j);
    uint4 z = make_uint4(0, 0, 0, 0);
    *(uint4*)(pad + ((size_t)bb * SPAD + p) * DD + c * 8) = z;
}

// transpose dw_w (o,i,k) -> Wc[k][i][o] via smem tiles (row 9: 2-way max conflicts)
__global__ void prep_wc_k(const float* __restrict__ dw_w, bf16* __restrict__ Wc) {
    __shared__ bf16 s[1024][9];    // [o_local*32 + i_local][k]
    int o0 = (blockIdx.x & 15) * 32;
    int i0 = (blockIdx.x >> 4) * 32;
    int t = threadIdx.x;           // 256 threads
    for (int p = t; p < 1024; p += 256) {
        int ol = p >> 5, il = p & 31;
        const float* src = dw_w + ((size_t)(o0 + ol) * DD + (i0 + il)) * KCONV;
        #pragma unroll
        for (int k = 0; k < KCONV; k++) s[p][k] = __float2bfloat16(src[k]);
    }
    __syncthreads();
    #pragma unroll
    for (int k = 0; k < KCONV; k++) {
        for (int e = t; e < 1024; e += 256) {
            int il = e >> 5, ol = e & 31;
            Wc[(size_t)k * DD * DD + (size_t)(i0 + il) * DD + (o0 + ol)] = s[ol * 32 + il][k];
        }
    }
}

// ---------------- fused scan: chunk aggregate + cross-chunk prefix + emit ----------------
// One kernel replaces scanA/scanB/scanC. Coefficients live in registers between phases.
// block: batch = bx>>6, d0 = (bx&63)*8; thread: chunk = t>>3 (0..31), dl = t&7.
__global__ void __launch_bounds__(256, 1)
scan_fused_k(const float2* __restrict__ AB, const float* __restrict__ l2,
             const float* __restrict__ x, float* __restrict__ x1) {
    int bx = blockIdx.x;
    int batch = bx >> 6;
    int d0 = (bx & 63) * 8;
    int t = threadIdx.x;
    int chunk = t >> 3;
    int dl = t & 7;
    int d = d0 + dl;
    size_t base = ((size_t)batch * SS + (size_t)chunk * LCH) * DD + d;

    float2 ab[LCH];
    #pragma unroll
    for (int s = 0; s < LCH; s++) ab[s] = AB[base + (size_t)s * DD];

    // phase 1: per-chunk aggregate (same order as old scanA)
    float A = 1.f, Bv = 0.f;
    #pragma unroll
    for (int s = 0; s < LCH; s++) { Bv = ab[s].x * Bv + ab[s].y; A *= ab[s].x; }

    __shared__ float sA[NC][8], sB[NC][8];
    sA[chunk][dl] = A;
    sB[chunk][dl] = Bv;
    __syncthreads();

    // phase 2: serial cross-chunk exclusive prefix per d (same order as old scanB)
    if (t < 8) {
        float h = 0.f;
        #pragma unroll
        for (int c = 0; c < NC; c++) {
            float a = sA[c][t], b = sB[c][t];
            sB[c][t] = h;           // exclusive prefix
            h = a * h + b;
        }
    }
    __syncthreads();

    // phase 3: emit x1 = h*gelu(l2) + skip (same order as old scanC)
    float h = sB[chunk][dl];
    #pragma unroll
    for (int s = 0; s < LCH; s++) {
        size_t idx = base + (size_t)s * DD;
        h = ab[s].x * h + ab[s].y;
        x1[idx] = h * gelu_exact(l2[idx]) + x[idx];
    }
}

// ---------------- launch ----------------
extern "C" void kernel_launch(void* const* d_in, const int* in_sizes, int n_in,
                              void* d_out, int out_size) {
    const float* x    = (const float*)d_in[0];
    const float* g    = (const float*)d_in[1];
    const float* W1   = (const float*)d_in[2];
    const float* b1   = (const float*)d_in[3];
    const float* W2   = (const float*)d_in[4];
    const float* b2   = (const float*)d_in[5];
    const float* dw_w = (const float*)d_in[6];
    const float* dw_b = (const float*)d_in[7];
    const float* pw_w = (const float*)d_in[8];
    const float* pw_b = (const float*)d_in[9];
    const float* Wi   = (const float*)d_in[10];
    const float* bi   = (const float*)d_in[11];
    const float* Wr   = (const float*)d_in[12];
    const float* br   = (const float*)d_in[13];
    const float* lam  = (const float*)d_in[14];
    const float* Wm1  = (const float*)d_in[15];
    const float* bm1  = (const float*)d_in[16];
    const float* Wm2  = (const float*)d_in[17];
    const float* bm2  = (const float*)d_in[18];
    float* out = (float*)d_out;

    bf16 *xn, *pad, *conv, *xL, *xn2, *act, *Wc, *pwT;
    bf16 *W12t, *Writ, *Wm1t, *Wm2t;
    float *l2, *AB, *x1, *lamc, *bri, *b12;
    cudaGetSymbolAddress((void**)&xn,   g_xn);
    cudaGetSymbolAddress((void**)&l2,   g_l2);
    cudaGetSymbolAddress((void**)&pad,  g_pad);
    cudaGetSymbolAddress((void**)&conv, g_conv);
    cudaGetSymbolAddress((void**)&xL,   g_xL);
    cudaGetSymbolAddress((void**)&AB,   g_AB);
    cudaGetSymbolAddress((void**)&x1,   g_x1);
    cudaGetSymbolAddress((void**)&xn2,  g_xn2);
    cudaGetSymbolAddress((void**)&act,  g_act);
    cudaGetSymbolAddress((void**)&Wc,   g_Wc);
    cudaGetSymbolAddress((void**)&pwT,  g_pwT);
    cudaGetSymbolAddress((void**)&lamc, g_lamc);
    cudaGetSymbolAddress((void**)&W12t, g_W12t);
    cudaGetSymbolAddress((void**)&b12,  g_b12);
    cudaGetSymbolAddress((void**)&Writ, g_Writ);
    cudaGetSymbolAddress((void**)&bri,  g_bri);
    cudaGetSymbolAddress((void**)&Wm1t, g_Wm1t);
    cudaGetSymbolAddress((void**)&Wm2t, g_Wm2t);

    cudaFuncSetAttribute(tgemm<5,false,false,false>, cudaFuncAttributeMaxDynamicSharedMemorySize, SMEMSZ);
    cudaFuncSetAttribute(tgemm<0,true ,true ,false>, cudaFuncAttributeMaxDynamicSharedMemorySize, SMEMSZ);
    cudaFuncSetAttribute(tgemm<0,false,true ,false>, cudaFuncAttributeMaxDynamicSharedMemorySize, SMEMSZ);
    cudaFuncSetAttribute(tgemm<4,false,false,false>, cudaFuncAttributeMaxDynamicSharedMemorySize, SMEMSZ);
    cudaFuncSetAttribute(tgemm<2,false,true ,false>, cudaFuncAttributeMaxDynamicSharedMemorySize, SMEMSZ);
    cudaFuncSetAttribute(tgemm<3,false,false,false>, cudaFuncAttributeMaxDynamicSharedMemorySize, SMEMSZ);

    dim3 g512 (DD / BN, MM / BM);          // (4, 128)
    dim3 g1024(2 * DD / BN, MM / BM);      // (8, 128)
    dim3 g2048(DM / BN, MM / BM);          // (16, 128)

    // ---- weight prep ----
    prep_weights_k<<<4608, 256>>>(W1, W2, Wm1, Wm2, pw_w, Wr, Wi,
                                  W12t, Wm1t, Wm2t, pwT, Writ);
    prep_small_k<<<18, 256>>>(br, bi, b1, b2, lam, bri, b12, lamc, pad);
    prep_wc_k<<<256, 256>>>(dw_w, Wc);

    // ---- block 1 ----
    rms_k<<<MM / 8, 256>>>(x, g, xn);
    tgemm<5,false,false,false><<<g1024, 256, SMEMSZ>>>(xn, W12t, b12, l2, nullptr, pad, MM, 2 * DD, DD);
    tgemm<0,true ,true ,false><<<g512, 256, SMEMSZ>>>(pad, Wc, dw_b, nullptr, nullptr, conv, MM, DD, KCONV * DD);
    tgemm<0,false,true ,false><<<g512, 256, SMEMSZ>>>(conv, pwT, pw_b, nullptr, nullptr, xL, MM, DD, DD);
    tgemm<4,false,false,false><<<g1024, 256, SMEMSZ>>>(xL, Writ, bri, nullptr, lamc, AB, MM, 2 * DD, DD);
    scan_fused_k<<<BB * 64, 256>>>((const float2*)AB, l2, x, x1);

    // ---- block 2 (MLP) ----
    rms_k<<<MM / 8, 256>>>(x1, g, xn2);
    tgemm<2,false,true ,false><<<g2048, 256, SMEMSZ>>>(xn2, Wm1t, bm1, nullptr, nullptr, act, MM, DM, DD);
    tgemm<3,false,false,false><<<g512, 256, SMEMSZ>>>(act, Wm2t, bm2, x1, nullptr, out, MM, DD, DM);
}

// round 14
// speedup vs baseline: 1.3488x; 1.0046x over previous
#include <cuda_runtime.h>
#include <cuda_bf16.h>
#include <math.h>

// ---------------- problem constants ----------------
#define BB    8
#define SS    2048
#define DD    512
#define MM    (BB*SS)          // 16384 rows
#define DM    (DD*4)           // 2048
#define KCONV 9
#define SPAD  (SS+8)           // 2056 padded rows per batch
#define NC    32               // scan chunks
#define LCH   (SS/NC)          // 64 steps per chunk

typedef __nv_bfloat16 bf16;
typedef __nv_bfloat162 bf162;

// ---------------- scratch (device globals; no allocs allowed) ----------------
__device__ bf16  g_xn  [MM*DD];
__device__ bf16  g_gl2 [MM*DD];     // gelu(l2) precomputed in GEMM epilogue, bf16
__device__ bf16  g_pad [BB*SPAD*DD];
__device__ bf16  g_conv[MM*DD];
__device__ bf16  g_xL  [MM*DD];
__device__ float g_AB  [2*MM*DD];   // interleaved scan coefficients {a,b} per (m,d)
__device__ float g_x1  [MM*DD];
__device__ bf16  g_xn2 [MM*DD];
__device__ bf16  g_act [MM*DM];
__device__ bf16  g_Wc  [KCONV*DD*DD];
__device__ bf16  g_pwT [DD*DD];
__device__ float g_lamc[DD];
__device__ bf16  g_W12t[DD*2*DD];   // [K=512][1024]: cols 0..511 = W1, 512..1023 = W2
__device__ float g_b12 [2*DD];
__device__ bf16  g_Writ[DD*2*DD];   // interleaved [K=512][2*512]: 2d=Wr, 2d+1=Wi
__device__ float g_bri [2*DD];
__device__ bf16  g_Wm1t[DD*DM];
__device__ bf16  g_Wm2t[DD*DM];

// ---------------- helpers ----------------
__device__ __forceinline__ float gelu_exact(float v) {
    return 0.5f * v * (1.0f + erff(v * 0.70710678118654752f));
}

__device__ __forceinline__ void mma16(float* c, const unsigned* a, const unsigned* b) {
    asm volatile(
        "mma.sync.aligned.m16n8k16.row.col.f32.bf16.bf16.f32 "
        "{%0,%1,%2,%3}, {%4,%5,%6,%7}, {%8,%9}, {%0,%1,%2,%3};"
        : "+f"(c[0]), "+f"(c[1]), "+f"(c[2]), "+f"(c[3])
        : "r"(a[0]), "r"(a[1]), "r"(a[2]), "r"(a[3]), "r"(b[0]), "r"(b[1]));
}

__device__ __forceinline__ void ldsm4(unsigned* r, unsigned addr) {
    asm volatile("ldmatrix.sync.aligned.m8n8.x4.shared.b16 {%0,%1,%2,%3}, [%4];"
                 : "=r"(r[0]), "=r"(r[1]), "=r"(r[2]), "=r"(r[3]) : "r"(addr));
}
__device__ __forceinline__ void ldsm2t(unsigned* r, unsigned addr) {
    asm volatile("ldmatrix.sync.aligned.m8n8.x2.trans.shared.b16 {%0,%1}, [%2];"
                 : "=r"(r[0]), "=r"(r[1]) : "r"(addr));
}

__device__ __forceinline__ void cpa16(unsigned s, const void* g) {
    asm volatile("cp.async.ca.shared.global [%0], [%1], 16;" :: "r"(s), "l"(g));
}
__device__ __forceinline__ void cpa_commit() {
    asm volatile("cp.async.commit_group;");
}

// ---------------- RMS norm, warp-per-row (f32 in -> bf16 out) ----------------
__global__ void rms_k(const float* __restrict__ x, const float* __restrict__ g,
                      bf16* __restrict__ o) {
    int row = blockIdx.x * 8 + (threadIdx.x >> 5);
    int lane = threadIdx.x & 31;
    const float4* xr = (const float4*)(x + (size_t)row * DD);
    float4 v[4];
    float s = 0.f;
    #pragma unroll
    for (int j = 0; j < 4; j++) {
        v[j] = xr[lane + 32 * j];
        s += v[j].x*v[j].x + v[j].y*v[j].y + v[j].z*v[j].z + v[j].w*v[j].w;
    }
    #pragma unroll
    for (int off = 16; off; off >>= 1) s += __shfl_xor_sync(0xffffffffu, s, off);
    float sc = 22.627416997969522f / (sqrtf(s) + 1e-6f);
    bf162* ob = (bf162*)(o + (size_t)row * DD);
    #pragma unroll
    for (int j = 0; j < 4; j++) {
        float4 gv = ((const float4*)g)[lane + 32 * j];
        int idx = 2 * (lane + 32 * j);
        ob[idx]     = __floats2bfloat162_rn(v[j].x * sc * gv.x, v[j].y * sc * gv.y);
        ob[idx + 1] = __floats2bfloat162_rn(v[j].z * sc * gv.z, v[j].w * sc * gv.w);
    }
}

// ---------------- bf16 tensor-core GEMM, 128x128 tile (round-8 proven config) ----------------
// EPI: 0 = bias, 2 = gelu(v)*v, 3 = +res, 4 = fused RG-LRU gates -> float2 {a,b},
//      5 = dual W1/W2 (cols<512 -> bf16 pad w/ remap, cols>=512 -> bf16 gelu(l2))
// CONV: A read from padded activations with tap offsets (K'=9*512)
// OUTBF: output bf16, else f32. PADOUT: padded-row output remap.
#define BM 128
#define BN 128
#define BK 32
#define APITCH 40      // 80B rows, conflict-free ldsm
#define BPITCH 136     // 272B rows
#define NSTG 3
#define SMEMSZ (NSTG*(BM*APITCH + BK*BPITCH)*2)

template <int EPI, bool CONV, bool OUTBF, bool PADOUT>
__global__ void __launch_bounds__(256, 2)
tgemm(const bf16* __restrict__ A, const bf16* __restrict__ Bw,
      const float* __restrict__ bias, float* __restrict__ res,
      const float* __restrict__ lamc, void* __restrict__ Cv,
      int M_, int N_, int K_) {
    extern __shared__ bf16 smb[];
    bf16 (*As)[BM][APITCH] = (bf16(*)[BM][APITCH])smb;
    bf16 (*Bs)[BK][BPITCH] = (bf16(*)[BK][BPITCH])(smb + NSTG * BM * APITCH);

    const int tid = threadIdx.x;
    const int m0 = blockIdx.y * BM;
    const int n0 = blockIdx.x * BN;
    const int warp = tid >> 5, lane = tid & 31;
    const int wm = (warp >> 2) * 64;
    const int wn = (warp & 3) * 32;
    const int padbase = CONV ? (m0 + 8 * (m0 / SS)) : 0;

    // cp.async staging
    const int arow = tid >> 1;          // 0..127
    const int acol = (tid & 1) * 16;    // 0 or 16
    const int brow = tid >> 3;          // 0..31
    const int bcol = (tid & 7) * 16;    // 0..112

    // ldmatrix lane offsets
    const int a_rowoff = (lane & 7) + ((lane >> 3) & 1) * 8;
    const int a_coloff = (lane >> 4) * 8;
    const int b_rowoff = lane & 15;

    const unsigned sA = (unsigned)__cvta_generic_to_shared(smb);
    const unsigned sB = (unsigned)__cvta_generic_to_shared(smb + NSTG * BM * APITCH);
    const unsigned aBase = sA + (unsigned)(((wm + a_rowoff) * APITCH + a_coloff) * 2);
    const unsigned bBase = sB + (unsigned)((b_rowoff * BPITCH + wn) * 2);

    const int nit = K_ / BK;

    auto prefetch = [&](int it, int buf) {
        int k0 = it * BK;
        const bf16* ga;
        if (CONV) {
            int tap = k0 >> 9;
            int kin = k0 & 511;
            ga = A + (size_t)(padbase + arow + tap) * DD + kin + acol;
        } else {
            ga = A + (size_t)(m0 + arow) * K_ + k0 + acol;
        }
        unsigned da = (unsigned)__cvta_generic_to_shared(&As[buf][arow][acol]);
        cpa16(da, ga);
        cpa16(da + 16, ga + 8);
        const bf16* gb = Bw + (size_t)(k0 + brow) * N_ + n0 + bcol;
        unsigned db = (unsigned)__cvta_generic_to_shared(&Bs[buf][brow][bcol]);
        cpa16(db, gb);
        cpa16(db + 16, gb + 8);
    };

    float acc[4][4][4] = {};

    prefetch(0, 0); cpa_commit();
    if (nit > 1) { prefetch(1, 1); cpa_commit(); }

    for (int it = 0; it < nit; it++) {
        if (it + 1 < nit) asm volatile("cp.async.wait_group 1;");
        else              asm volatile("cp.async.wait_group 0;");
        __syncthreads();
        if (it + 2 < nit) { prefetch(it + 2, (it + 2) % NSTG); cpa_commit(); }

        const int buf = it % NSTG;
        const unsigned ab = aBase + (unsigned)(buf * BM * APITCH * 2);
        const unsigned bb = bBase + (unsigned)(buf * BK * BPITCH * 2);
        #pragma unroll
        for (int t = 0; t < 2; t++) {
            unsigned af[4][4], bfr[4][2];
            #pragma unroll
            for (int mi = 0; mi < 4; mi++)
                ldsm4(af[mi], ab + (unsigned)((mi * 16 * APITCH + 16 * t) * 2));
            #pragma unroll
            for (int ni = 0; ni < 4; ni++)
                ldsm2t(bfr[ni], bb + (unsigned)((16 * t * BPITCH + 8 * ni) * 2));
            #pragma unroll
            for (int mi = 0; mi < 4; mi++)
                #pragma unroll
                for (int ni = 0; ni < 4; ni++)
                    mma16(acc[mi][ni], af[mi], bfr[ni]);
        }
        // single barrier per iteration is sufficient with NSTG=3
    }

    // epilogue
    const int r = lane >> 2, cg = lane & 3;
    const int opitch = PADOUT ? DD : N_;
    #pragma unroll
    for (int mi = 0; mi < 4; mi++) {
        int mlo = m0 + wm + mi * 16 + r;
        int mhi = mlo + 8;
        int olo = PADOUT ? (mlo + 4 + 8 * (mlo >> 11)) : mlo;
        int ohi = PADOUT ? (mhi + 4 + 8 * (mhi >> 11)) : mhi;
        #pragma unroll
        for (int ni = 0; ni < 4; ni++) {
            int n = n0 + wn + ni * 8 + 2 * cg;
            float b0 = bias[n], b1 = bias[n + 1];
            float v0 = acc[mi][ni][0] + b0;
            float v1 = acc[mi][ni][1] + b1;
            float v2 = acc[mi][ni][2] + b0;
            float v3 = acc[mi][ni][3] + b1;
            if (EPI == 4) {
                int d = n >> 1;
                float lc = lamc[d];
                float r0 = 1.f / (1.f + __expf(-v0));
                float i0 = 1.f / (1.f + __expf(-v1));
                float r1 = 1.f / (1.f + __expf(-v2));
                float i1 = 1.f / (1.f + __expf(-v3));
                float a0 = __expf(lc * r0), a1 = __expf(lc * r1);
                float xl0 = __bfloat162float(A[(size_t)mlo * DD + d]);
                float xl1 = __bfloat162float(A[(size_t)mhi * DD + d]);
                float bb0 = sqrtf(fmaxf(0.f, 1.f - a0 * a0)) * i0 * xl0;
                float bb1 = sqrtf(fmaxf(0.f, 1.f - a1 * a1)) * i1 * xl1;
                float2* ABp = (float2*)Cv;
                ABp[(size_t)mlo * DD + d] = make_float2(a0, bb0);
                ABp[(size_t)mhi * DD + d] = make_float2(a1, bb1);
                continue;
            }
            if (EPI == 5) {
                if (n0 < DD) {
                    bf16* C = (bf16*)Cv;
                    int plo = mlo + 4 + 8 * (mlo >> 11);
                    int phi = mhi + 4 + 8 * (mhi >> 11);
                    *(bf162*)(C + (size_t)plo * DD + n) = __floats2bfloat162_rn(v0, v1);
                    *(bf162*)(C + (size_t)phi * DD + n) = __floats2bfloat162_rn(v2, v3);
                } else {
                    // W2 half: store gelu(l2) directly as bf16
                    int c = n - DD;
                    bf16* G = (bf16*)res;
                    float g0 = gelu_exact(v0), g1 = gelu_exact(v1);
                    float g2 = gelu_exact(v2), g3 = gelu_exact(v3);
                    *(bf162*)(G + (size_t)mlo * DD + c) = __floats2bfloat162_rn(g0, g1);
                    *(bf162*)(G + (size_t)mhi * DD + c) = __floats2bfloat162_rn(g2, g3);
                }
                continue;
            }
            if (EPI == 2) {
                v0 *= gelu_exact(v0); v1 *= gelu_exact(v1);
                v2 *= gelu_exact(v2); v3 *= gelu_exact(v3);
            } else if (EPI == 3) {
                float2 r0 = *(const float2*)(res + (size_t)mlo * N_ + n);
                float2 r1 = *(const float2*)(res + (size_t)mhi * N_ + n);
                v0 += r0.x; v1 += r0.y; v2 += r1.x; v3 += r1.y;
            }
            if (OUTBF) {
                bf16* C = (bf16*)Cv;
                *(bf162*)(C + (size_t)olo * opitch + n) = __floats2bfloat162_rn(v0, v1);
                *(bf162*)(C + (size_t)ohi * opitch + n) = __floats2bfloat162_rn(v2, v3);
            } else {
                float* C = (float*)Cv;
                *(float2*)(C + (size_t)olo * opitch + n) = make_float2(v0, v1);
                *(float2*)(C + (size_t)ohi * opitch + n) = make_float2(v2, v3);
            }
        }
    }
}

// ---------------- weight prep (merged, ranged dispatch) ----------------
__global__ void prep_weights_k(const float* __restrict__ W1, const float* __restrict__ W2,
                               const float* __restrict__ Wm1, const float* __restrict__ Wm2,
                               const float* __restrict__ pw_w,
                               const float* __restrict__ Wr, const float* __restrict__ Wi,
                               bf16* __restrict__ W12t, bf16* __restrict__ Wm1t,
                               bf16* __restrict__ Wm2t, bf16* __restrict__ pwT,
                               bf16* __restrict__ Writ) {
    int b = blockIdx.x, tid = threadIdx.x;
    if (b < 512) {
        const float* s = (b < 256) ? W1 : W2;
        int coff = (b < 256) ? 0 : DD;
        int i = ((b & 255) * 256 + tid);            // float4 index, 65536 total
        float4 v = ((const float4*)s)[i];
        int k = i >> 7;
        int c = (i & 127) * 4 + coff;
        bf162* d = (bf162*)(W12t + (size_t)k * (2 * DD) + c);
        d[0] = __floats2bfloat162_rn(v.x, v.y);
        d[1] = __floats2bfloat162_rn(v.z, v.w);
        return;
    }
    if (b < 2560) {
        const float* s = (b < 1536) ? Wm1 : Wm2;
        bf16* d = (b < 1536) ? Wm1t : Wm2t;
        int j = ((b < 1536) ? (b - 512) : (b - 1536)) * 256 + tid;  // float4 idx, 262144
        float4 v = ((const float4*)s)[j];
        ((bf162*)d)[2*j]   = __floats2bfloat162_rn(v.x, v.y);
        ((bf162*)d)[2*j+1] = __floats2bfloat162_rn(v.z, v.w);
        return;
    }
    if (b < 3584) {
        int idx = (b - 2560) * 256 + tid;           // 262144 elements
        int o = idx % DD;
        int i = idx / DD;
        pwT[idx] = __float2bfloat16(pw_w[(size_t)o * DD + i]);
        return;
    }
    {
        int idx = (b - 3584) * 256 + tid;           // 262144 elements
        int k = idx / DD, d = idx % DD;
        Writ[(size_t)k * (2 * DD) + 2 * d]     = __float2bfloat16(Wr[idx]);
        Writ[(size_t)k * (2 * DD) + 2 * d + 1] = __float2bfloat16(Wi[idx]);
    }
}

// small vectors + pad-halo zeroing, ranged dispatch:
// blocks 0..1 : bri/b12/lamc ; blocks 2..17 : zero pad edges
__global__ void prep_small_k(const float* __restrict__ br, const float* __restrict__ bi,
                             const float* __restrict__ b1, const float* __restrict__ b2,
                             const float* __restrict__ lam,
                             float* __restrict__ bri, float* __restrict__ b12,
                             float* __restrict__ lamc, bf16* __restrict__ pad) {
    int b = blockIdx.x, tid = threadIdx.x;
    if (b < 2) {
        int d = b * 256 + tid;
        bri[2 * d]     = br[d];
        bri[2 * d + 1] = bi[d];
        b12[d]        = b1[d];
        b12[DD + d]   = b2[d];
        float l = lam[d];
        float sp = (l > 15.f) ? l : log1pf(expf(l));
        lamc[d] = -8.0f * sp;
        return;
    }
    int idx = (b - 2) * 256 + tid;      // 4096 chunks of 8 bf16
    int c = idx & 63;
    int rr = idx >> 6;
    int bb = rr >> 3, j = rr & 7;
    int p = (j < 4) ? j : (2048 + j);
    uint4 z = make_uint4(0, 0, 0, 0);
    *(uint4*)(pad + ((size_t)bb * SPAD + p) * DD + c * 8) = z;
}

// transpose dw_w (o,i,k) -> Wc[k][i][o] via smem tiles (row 9: 2-way max conflicts)
__global__ void prep_wc_k(const float* __restrict__ dw_w, bf16* __restrict__ Wc) {
    __shared__ bf16 s[1024][9];    // [o_local*32 + i_local][k]
    int o0 = (blockIdx.x & 15) * 32;
    int i0 = (blockIdx.x >> 4) * 32;
    int t = threadIdx.x;           // 256 threads
    for (int p = t; p < 1024; p += 256) {
        int ol = p >> 5, il = p & 31;
        const float* src = dw_w + ((size_t)(o0 + ol) * DD + (i0 + il)) * KCONV;
        #pragma unroll
        for (int k = 0; k < KCONV; k++) s[p][k] = __float2bfloat16(src[k]);
    }
    __syncthreads();
    #pragma unroll
    for (int k = 0; k < KCONV; k++) {
        for (int e = t; e < 1024; e += 256) {
            int il = e >> 5, ol = e & 31;
            Wc[(size_t)k * DD * DD + (size_t)(i0 + il) * DD + (o0 + ol)] = s[ol * 32 + il][k];
        }
    }
}

// ---------------- fused scan: chunk aggregate + cross-chunk prefix + emit ----------------
// block: batch = bx>>6, d0 = (bx&63)*8; thread: chunk = t>>3 (0..31), dl = t&7.
__global__ void __launch_bounds__(256, 1)
scan_fused_k(const float2* __restrict__ AB, const bf16* __restrict__ gl2,
             const float* __restrict__ x, float* __restrict__ x1) {
    int bx = blockIdx.x;
    int batch = bx >> 6;
    int d0 = (bx & 63) * 8;
    int t = threadIdx.x;
    int chunk = t >> 3;
    int dl = t & 7;
    int d = d0 + dl;
    size_t base = ((size_t)batch * SS + (size_t)chunk * LCH) * DD + d;

    float2 ab[LCH];
    #pragma unroll
    for (int s = 0; s < LCH; s++) ab[s] = AB[base + (size_t)s * DD];

    // phase 1: per-chunk aggregate
    float A = 1.f, Bv = 0.f;
    #pragma unroll
    for (int s = 0; s < LCH; s++) { Bv = ab[s].x * Bv + ab[s].y; A *= ab[s].x; }

    __shared__ float sA[NC][8], sB[NC][8];
    sA[chunk][dl] = A;
    sB[chunk][dl] = Bv;
    __syncthreads();

    // phase 2: serial cross-chunk exclusive prefix per d
    if (t < 8) {
        float h = 0.f;
        #pragma unroll
        for (int c = 0; c < NC; c++) {
            float a = sA[c][t], b = sB[c][t];
            sB[c][t] = h;           // exclusive prefix
            h = a * h + b;
        }
    }
    __syncthreads();

    // phase 3: emit x1 = h*gelu_l2 + skip
    float h = sB[chunk][dl];
    #pragma unroll
    for (int s = 0; s < LCH; s++) {
        size_t idx = base + (size_t)s * DD;
        h = ab[s].x * h + ab[s].y;
        x1[idx] = h * __bfloat162float(gl2[idx]) + x[idx];
    }
}

// ---------------- launch ----------------
extern "C" void kernel_launch(void* const* d_in, const int* in_sizes, int n_in,
                              void* d_out, int out_size) {
    const float* x    = (const float*)d_in[0];
    const float* g    = (const float*)d_in[1];
    const float* W1   = (const float*)d_in[2];
    const float* b1   = (const float*)d_in[3];
    const float* W2   = (const float*)d_in[4];
    const float* b2   = (const float*)d_in[5];
    const float* dw_w = (const float*)d_in[6];
    const float* dw_b = (const float*)d_in[7];
    const float* pw_w = (const float*)d_in[8];
    const float* pw_b = (const float*)d_in[9];
    const float* Wi   = (const float*)d_in[10];
    const float* bi   = (const float*)d_in[11];
    const float* Wr   = (const float*)d_in[12];
    const float* br   = (const float*)d_in[13];
    const float* lam  = (const float*)d_in[14];
    const float* Wm1  = (const float*)d_in[15];
    const float* bm1  = (const float*)d_in[16];
    const float* Wm2  = (const float*)d_in[17];
    const float* bm2  = (const float*)d_in[18];
    float* out = (float*)d_out;

    bf16 *xn, *gl2, *pad, *conv, *xL, *xn2, *act, *Wc, *pwT;
    bf16 *W12t, *Writ, *Wm1t, *Wm2t;
    float *AB, *x1, *lamc, *bri, *b12;
    cudaGetSymbolAddress((void**)&xn,   g_xn);
    cudaGetSymbolAddress((void**)&gl2,  g_gl2);
    cudaGetSymbolAddress((void**)&pad,  g_pad);
    cudaGetSymbolAddress((void**)&conv, g_conv);
    cudaGetSymbolAddress((void**)&xL,   g_xL);
    cudaGetSymbolAddress((void**)&AB,   g_AB);
    cudaGetSymbolAddress((void**)&x1,   g_x1);
    cudaGetSymbolAddress((void**)&xn2,  g_xn2);
    cudaGetSymbolAddress((void**)&act,  g_act);
    cudaGetSymbolAddress((void**)&Wc,   g_Wc);
    cudaGetSymbolAddress((void**)&pwT,  g_pwT);
    cudaGetSymbolAddress((void**)&lamc, g_lamc);
    cudaGetSymbolAddress((void**)&W12t, g_W12t);
    cudaGetSymbolAddress((void**)&b12,  g_b12);
    cudaGetSymbolAddress((void**)&Writ, g_Writ);
    cudaGetSymbolAddress((void**)&bri,  g_bri);
    cudaGetSymbolAddress((void**)&Wm1t, g_Wm1t);
    cudaGetSymbolAddress((void**)&Wm2t, g_Wm2t);

    cudaFuncSetAttribute(tgemm<5,false,false,false>, cudaFuncAttributeMaxDynamicSharedMemorySize, SMEMSZ);
    cudaFuncSetAttribute(tgemm<0,true ,true ,false>, cudaFuncAttributeMaxDynamicSharedMemorySize, SMEMSZ);
    cudaFuncSetAttribute(tgemm<0,false,true ,false>, cudaFuncAttributeMaxDynamicSharedMemorySize, SMEMSZ);
    cudaFuncSetAttribute(tgemm<4,false,false,false>, cudaFuncAttributeMaxDynamicSharedMemorySize, SMEMSZ);
    cudaFuncSetAttribute(tgemm<2,false,true ,false>, cudaFuncAttributeMaxDynamicSharedMemorySize, SMEMSZ);
    cudaFuncSetAttribute(tgemm<3,false,false,false>, cudaFuncAttributeMaxDynamicSharedMemorySize, SMEMSZ);

    dim3 g512 (DD / BN, MM / BM);          // (4, 128)
    dim3 g1024(2 * DD / BN, MM / BM);      // (8, 128)
    dim3 g2048(DM / BN, MM / BM);          // (16, 128)

    // ---- weight prep ----
    prep_weights_k<<<4608, 256>>>(W1, W2, Wm1, Wm2, pw_w, Wr, Wi,
                                  W12t, Wm1t, Wm2t, pwT, Writ);
    prep_small_k<<<18, 256>>>(br, bi, b1, b2, lam, bri, b12, lamc, pad);
    prep_wc_k<<<256, 256>>>(dw_w, Wc);

    // ---- block 1 ----
    rms_k<<<MM / 8, 256>>>(x, g, xn);
    tgemm<5,false,false,false><<<g1024, 256, SMEMSZ>>>(xn, W12t, b12, (float*)gl2, nullptr, pad, MM, 2 * DD, DD);
    tgemm<0,true ,true ,false><<<g512, 256, SMEMSZ>>>(pad, Wc, dw_b, nullptr, nullptr, conv, MM, DD, KCONV * DD);
    tgemm<0,false,true ,false><<<g512, 256, SMEMSZ>>>(conv, pwT, pw_b, nullptr, nullptr, xL, MM, DD, DD);
    tgemm<4,false,false,false><<<g1024, 256, SMEMSZ>>>(xL, Writ, bri, nullptr, lamc, AB, MM, 2 * DD, DD);
    scan_fused_k<<<BB * 64, 256>>>((const float2*)AB, gl2, x, x1);

    // ---- block 2 (MLP) ----
    rms_k<<<MM / 8, 256>>>(x1, g, xn2);
    tgemm<2,false,true ,false><<<g2048, 256, SMEMSZ>>>(xn2, Wm1t, bm1, nullptr, nullptr, act, MM, DM, DD);
    tgemm<3,false,false,false><<<g512, 256, SMEMSZ>>>(act, Wm2t, bm2, x1, nullptr, out, MM, DD, DM);
}